// round 15
// baseline (speedup 1.0000x reference)
#include <cuda_runtime.h>
#include <cuda_bf16.h>
#include <cstdint>

// ---------------- problem constants ----------------
#define BB   32
#define NTOK 4096
#define SS   24
#define DD   256
#define HH   4
#define DHH  64
#define SH   96              // SS*HH
#define ROWS_BIG (BB*NTOK)   // 131072
#define ROWS_SL  (BB*SS)     // 768
#define EPS   1e-8f
#define LN_EPS 1e-5f
#define SCALE 0.125f         // 64^-0.5

// ---------------- device scratch ----------------
__device__ float g_bufA[ROWS_BIG * DD];
__device__ __nv_bfloat16 g_Kh[ROWS_BIG * DD];
__device__ __nv_bfloat16 g_Kl[ROWS_BIG * DD];
__device__ float g_V[ROWS_BIG * DD];
__device__ __nv_bfloat16 g_P0h[ROWS_BIG * DD];
__device__ __nv_bfloat16 g_P0l[ROWS_BIG * DD];
__device__ __nv_bfloat16 g_P1h[ROWS_BIG * DD];
__device__ __nv_bfloat16 g_P1l[ROWS_BIG * DD];
__device__ __nv_bfloat16 g_W1h[DD * DD], g_W1l[DD * DD];
__device__ __nv_bfloat16 g_W2h[DD * DD], g_W2l[DD * DD];
__device__ __nv_bfloat16 g_Wkh[DD * DD], g_Wkl[DD * DD];
__device__ __nv_bfloat16 g_Wvh[DD * DD], g_Wvl[DD * DD];
__device__ float g_slots[ROWS_SL * DD];
__device__ float g_sn[ROWS_SL * DD];
__device__ __nv_bfloat16 g_qh[ROWS_SL * DD];
__device__ __nv_bfloat16 g_ql[ROWS_SL * DD];
__device__ float g_attn[(size_t)BB * SH * NTOK];
__device__ float g_updp[4 * ROWS_SL * DD];
__device__ float g_rsump[4 * BB * SH];
__device__ float g_upd[ROWS_SL * DD];
__device__ int   g_cnt[BB * HH];          // zero-init; self-resetting
__device__ float g_gi[ROWS_SL * 3 * DD];
__device__ float g_gh[ROWS_SL * 3 * DD];

// ---------------- helpers ----------------
__device__ __forceinline__ uint32_t smem_u32(const void* p) {
    uint32_t a;
    asm("{ .reg .u64 t; cvta.to.shared.u64 t, %1; cvt.u32.u64 %0, t; }" : "=r"(a) : "l"(p));
    return a;
}
__device__ __forceinline__ void cp16(uint32_t dst, const void* src) {
    asm volatile("cp.async.cg.shared.global [%0], [%1], 16;" :: "r"(dst), "l"(src));
}
#define CP_COMMIT() asm volatile("cp.async.commit_group;" ::: "memory")
#define CP_WAIT1()  asm volatile("cp.async.wait_group 1;" ::: "memory")
#define CP_WAIT0()  asm volatile("cp.async.wait_group 0;" ::: "memory")

#define LDSM_X4(R, ADDR) \
    asm volatile("ldmatrix.sync.aligned.m8n8.x4.shared.b16 {%0,%1,%2,%3}, [%4];" \
        : "=r"((R)[0]), "=r"((R)[1]), "=r"((R)[2]), "=r"((R)[3]) : "r"(ADDR))

#define MMA16816(C, A, B0, B1) \
    asm volatile("mma.sync.aligned.m16n8k16.row.col.f32.bf16.bf16.f32 " \
        "{%0,%1,%2,%3}, {%4,%5,%6,%7}, {%8,%9}, {%0,%1,%2,%3};" \
        : "+f"((C)[0]), "+f"((C)[1]), "+f"((C)[2]), "+f"((C)[3]) \
        : "r"((A)[0]), "r"((A)[1]), "r"((A)[2]), "r"((A)[3]), "r"(B0), "r"(B1))

__device__ __forceinline__ uint32_t pack_bf2(float a, float b, float* ra, float* rb) {
    __nv_bfloat16 ha = __float2bfloat16(a), hb = __float2bfloat16(b);
    *ra = a - __bfloat162float(ha);
    *rb = b - __bfloat162float(hb);
    return (uint32_t)__bfloat16_as_ushort(ha) | ((uint32_t)__bfloat16_as_ushort(hb) << 16);
}
__device__ __forceinline__ uint32_t pack_bf2_lo(float a, float b) {
    __nv_bfloat16 ha = __float2bfloat16(a), hb = __float2bfloat16(b);
    return (uint32_t)__bfloat16_as_ushort(ha) | ((uint32_t)__bfloat16_as_ushort(hb) << 16);
}

// ---------------- mma.sync split-bf16 GEMM, cp.async 2-stage pipelined ----------
#define TG_STAGE 51200
#define TG_SMEM  (2 * TG_STAGE)
#define TG_AL    5120
#define TG_WH    10240
#define TG_WL    30720

__global__ __launch_bounds__(256, 2) void gemm_mma(
    const __nv_bfloat16* __restrict__ Ah, const __nv_bfloat16* __restrict__ Al,
    const __nv_bfloat16* Wh_, const __nv_bfloat16* Wl_,
    const float* __restrict__ bias, float* Cf_,
    __nv_bfloat16* Chi, __nv_bfloat16* Clo, int relu,
    const __nv_bfloat16* Wh2, const __nv_bfloat16* Wl2, float* Cf2)
{
    extern __shared__ char smem[];
    const __nv_bfloat16* Wh = Wh_;
    const __nv_bfloat16* Wl = Wl_;
    float* Cf = Cf_;
    if (blockIdx.z == 1) { Wh = Wh2; Wl = Wl2; Cf = Cf2; Chi = nullptr; Clo = nullptr; }

    const int tid = threadIdx.x, lane = tid & 31, wid = tid >> 5;
    const int wm = wid >> 2, wn = wid & 3;
    const int bm = blockIdx.y * 64;
    const uint32_t sb = smem_u32(smem);

    const int r = tid >> 2, q = tid & 3;
    const uint32_t stA = (uint32_t)(r * 80 + q * 16);
    const size_t goA = (size_t)(bm + r) * 512 + q * 16;

    float acc[2][8][4];
#pragma unroll
    for (int i = 0; i < 2; i++)
#pragma unroll
        for (int j = 0; j < 8; j++)
#pragma unroll
            for (int e = 0; e < 4; e++) acc[i][j][e] = 0.f;

    {
        cp16(sb + stA,         (const char*)Ah + goA);
        cp16(sb + TG_AL + stA, (const char*)Al + goA);
#pragma unroll
        for (int u = 0; u < 4; u++) {
            uint32_t rw = (uint32_t)(r + 64 * u);
            uint32_t st = rw * 80 + q * 16;
            size_t go = (size_t)rw * 512 + q * 16;
            cp16(sb + TG_WH + st, (const char*)Wh + go);
            cp16(sb + TG_WL + st, (const char*)Wl + go);
        }
        CP_COMMIT();
    }

    for (int kc = 0; kc < 8; kc++) {
        if (kc < 7) {
            uint32_t d = sb + ((kc + 1) & 1) * TG_STAGE;
            size_t off = (size_t)(kc + 1) * 64;
            cp16(d + stA,         (const char*)Ah + goA + off);
            cp16(d + TG_AL + stA, (const char*)Al + goA + off);
#pragma unroll
            for (int u = 0; u < 4; u++) {
                uint32_t rw = (uint32_t)(r + 64 * u);
                uint32_t st = rw * 80 + q * 16;
                size_t go = (size_t)rw * 512 + q * 16 + off;
                cp16(d + TG_WH + st, (const char*)Wh + go);
                cp16(d + TG_WL + st, (const char*)Wl + go);
            }
            CP_COMMIT();
            CP_WAIT1();
        } else {
            CP_WAIT0();
        }
        __syncthreads();
        uint32_t stg = sb + (kc & 1) * TG_STAGE;
#pragma unroll
        for (int kk = 0; kk < 2; kk++) {
            uint32_t a_h[2][4], a_l[2][4], bfr[4][4];
            uint32_t acol  = kk * 32 + (lane >> 4) * 16;
            uint32_t arow0 = wm * 32 + (lane & 15);
            uint32_t bcol  = kk * 32 + ((lane >> 3) & 1) * 16;
            uint32_t nrowb = wn * 64 + ((lane >> 4) & 1) * 8 + (lane & 7);
            LDSM_X4(a_h[0], stg + arow0 * 80 + acol);
            LDSM_X4(a_h[1], stg + (arow0 + 16) * 80 + acol);
#pragma unroll
            for (int ng = 0; ng < 4; ng++)
                LDSM_X4(bfr[ng], stg + TG_WH + (nrowb + ng * 16) * 80 + bcol);
#pragma unroll
            for (int mt = 0; mt < 2; mt++)
#pragma unroll
                for (int nt = 0; nt < 8; nt++) {
                    int ng = nt >> 1, hb = (nt & 1) * 2;
                    MMA16816(acc[mt][nt], a_h[mt], bfr[ng][hb], bfr[ng][hb + 1]);
                }
            LDSM_X4(a_l[0], stg + TG_AL + arow0 * 80 + acol);
            LDSM_X4(a_l[1], stg + TG_AL + (arow0 + 16) * 80 + acol);
#pragma unroll
            for (int mt = 0; mt < 2; mt++)
#pragma unroll
                for (int nt = 0; nt < 8; nt++) {
                    int ng = nt >> 1, hb = (nt & 1) * 2;
                    MMA16816(acc[mt][nt], a_l[mt], bfr[ng][hb], bfr[ng][hb + 1]);
                }
#pragma unroll
            for (int ng = 0; ng < 4; ng++)
                LDSM_X4(bfr[ng], stg + TG_WL + (nrowb + ng * 16) * 80 + bcol);
#pragma unroll
            for (int mt = 0; mt < 2; mt++)
#pragma unroll
                for (int nt = 0; nt < 8; nt++) {
                    int ng = nt >> 1, hb = (nt & 1) * 2;
                    MMA16816(acc[mt][nt], a_h[mt], bfr[ng][hb], bfr[ng][hb + 1]);
                }
        }
        __syncthreads();
    }

    const int g = lane >> 2, tg = lane & 3;
#pragma unroll
    for (int mt = 0; mt < 2; mt++)
#pragma unroll
        for (int nt = 0; nt < 8; nt++)
#pragma unroll
            for (int half = 0; half < 2; half++) {
                int row = bm + wm * 32 + mt * 16 + g + half * 8;
                int col = wn * 64 + nt * 8 + tg * 2;
                float v0 = acc[mt][nt][half * 2 + 0];
                float v1 = acc[mt][nt][half * 2 + 1];
                if (bias) { v0 += bias[col]; v1 += bias[col + 1]; }
                if (relu) { v0 = fmaxf(v0, 0.f); v1 = fmaxf(v1, 0.f); }
                size_t o = (size_t)row * 256 + col;
                if (Cf) *(float2*)(Cf + o) = make_float2(v0, v1);
                if (Chi) {
                    float r0, r1;
                    uint32_t hp = pack_bf2(v0, v1, &r0, &r1);
                    *(uint32_t*)(Chi + o) = hp;
                    *(uint32_t*)(Clo + o) = pack_bf2_lo(r0, r1);
                }
            }
}

// ---------------- dots via mma: attn[b,i*4+h,n] = SCALE * q.K^T (split bf16) -----
#define DM_QH 0
#define DM_QL 4608
#define DM_KH 9216
#define DM_KL 46080
#define DM_SMEM 82944

__global__ __launch_bounds__(256, 2) void dots_mma(
    const __nv_bfloat16* __restrict__ qh, const __nv_bfloat16* __restrict__ ql,
    const __nv_bfloat16* __restrict__ Kh, const __nv_bfloat16* __restrict__ Kl,
    float* __restrict__ attn)
{
    extern __shared__ char smem[];
    const int b = blockIdx.z, h = blockIdx.y, n0 = blockIdx.x * 256;
    const int tid = threadIdx.x, lane = tid & 31, wn = tid >> 5;
    const uint32_t sb = smem_u32(smem);

#pragma unroll
    for (int u = 0; u < 8; u++) {
        int idx = u * 256 + tid;
        int row = idx >> 3, qq = idx & 7;
        uint32_t st = (uint32_t)(row * 144 + qq * 16);
        size_t go = ((size_t)(b * NTOK + n0 + row) * 256 + h * DHH) * 2 + qq * 16;
        cp16(sb + DM_KH + st, (const char*)Kh + go);
        cp16(sb + DM_KL + st, (const char*)Kl + go);
    }
    CP_COMMIT();
    {
        int row = tid >> 3, qq = tid & 7;
        uint32_t st = (uint32_t)(row * 144 + qq * 16);
        if (row < SS) {
            size_t go = ((size_t)(b * SS + row) * 256 + h * DHH) * 2 + qq * 16;
            *(uint4*)(smem + DM_QH + st) = *(const uint4*)((const char*)qh + go);
            *(uint4*)(smem + DM_QL + st) = *(const uint4*)((const char*)ql + go);
        } else {
            uint4 z = make_uint4(0, 0, 0, 0);
            *(uint4*)(smem + DM_QH + st) = z;
            *(uint4*)(smem + DM_QL + st) = z;
        }
    }
    CP_WAIT0();
    __syncthreads();

    float acc[2][4][4];
#pragma unroll
    for (int i = 0; i < 2; i++)
#pragma unroll
        for (int j = 0; j < 4; j++)
#pragma unroll
            for (int e = 0; e < 4; e++) acc[i][j][e] = 0.f;

#pragma unroll
    for (int ks = 0; ks < 4; ks++) {
        uint32_t a_h[2][4], a_l[2][4], bfr[2][4];
        uint32_t acol = ks * 32 + (lane >> 4) * 16;
        uint32_t arow = (uint32_t)(lane & 15);
        uint32_t bcol = ks * 32 + ((lane >> 3) & 1) * 16;
        uint32_t nrow = (uint32_t)(wn * 32 + ((lane >> 4) & 1) * 8 + (lane & 7));
        LDSM_X4(a_h[0], sb + DM_QH + arow * 144 + acol);
        LDSM_X4(a_h[1], sb + DM_QH + (arow + 16) * 144 + acol);
        LDSM_X4(bfr[0], sb + DM_KH + nrow * 144 + bcol);
        LDSM_X4(bfr[1], sb + DM_KH + (nrow + 16) * 144 + bcol);
#pragma unroll
        for (int mt = 0; mt < 2; mt++)
#pragma unroll
            for (int nt = 0; nt < 4; nt++) {
                int ng = nt >> 1, hb = (nt & 1) * 2;
                MMA16816(acc[mt][nt], a_h[mt], bfr[ng][hb], bfr[ng][hb + 1]);
            }
        LDSM_X4(a_l[0], sb + DM_QL + arow * 144 + acol);
        LDSM_X4(a_l[1], sb + DM_QL + (arow + 16) * 144 + acol);
#pragma unroll
        for (int mt = 0; mt < 2; mt++)
#pragma unroll
            for (int nt = 0; nt < 4; nt++) {
                int ng = nt >> 1, hb = (nt & 1) * 2;
                MMA16816(acc[mt][nt], a_l[mt], bfr[ng][hb], bfr[ng][hb + 1]);
            }
        LDSM_X4(bfr[0], sb + DM_KL + nrow * 144 + bcol);
        LDSM_X4(bfr[1], sb + DM_KL + (nrow + 16) * 144 + bcol);
#pragma unroll
        for (int mt = 0; mt < 2; mt++)
#pragma unroll
            for (int nt = 0; nt < 4; nt++) {
                int ng = nt >> 1, hb = (nt & 1) * 2;
                MMA16816(acc[mt][nt], a_h[mt], bfr[ng][hb], bfr[ng][hb + 1]);
            }
    }

    const int g = lane >> 2, tg = lane & 3;
#pragma unroll
    for (int mt = 0; mt < 2; mt++)
#pragma unroll
        for (int nt = 0; nt < 4; nt++)
#pragma unroll
            for (int half = 0; half < 2; half++) {
                if (mt == 1 && half == 1) continue;
                int row = mt * 16 + g + half * 8;
                int col = n0 + wn * 32 + nt * 8 + tg * 2;
                float v0 = acc[mt][nt][half * 2 + 0] * SCALE;
                float v1 = acc[mt][nt][half * 2 + 1] * SCALE;
                *(float2*)(attn + ((size_t)b * SH + row * HH + h) * NTOK + col)
                    = make_float2(v0, v1);
            }
}

// ---------------- W transpose + bf16 split (4 weights, one launch) ----------------
__global__ void convert_w4(
    const float* __restrict__ W0, __nv_bfloat16* __restrict__ H0, __nv_bfloat16* __restrict__ L0,
    const float* __restrict__ W1, __nv_bfloat16* __restrict__ H1, __nv_bfloat16* __restrict__ L1,
    const float* __restrict__ W2, __nv_bfloat16* __restrict__ H2, __nv_bfloat16* __restrict__ L2,
    const float* __restrict__ W3, __nv_bfloat16* __restrict__ H3, __nv_bfloat16* __restrict__ L3)
{
    const float* W; __nv_bfloat16 *Hh, *Hl;
    switch (blockIdx.y) {
        case 0: W = W0; Hh = H0; Hl = L0; break;
        case 1: W = W1; Hh = H1; Hl = L1; break;
        case 2: W = W2; Hh = H2; Hl = L2; break;
        default: W = W3; Hh = H3; Hl = L3; break;
    }
    int k = blockIdx.x;
    int n = threadIdx.x;
    float v = W[k * DD + n];
    __nv_bfloat16 h = __float2bfloat16(v);
    Hh[n * DD + k] = h;
    Hl[n * DD + k] = __float2bfloat16(v - __bfloat162float(h));
}

// ---------------- LayerNorm (fp32 out, slots path) ----------------
__global__ void ln_kernel(const float* __restrict__ x, const float* __restrict__ g,
                          const float* __restrict__ b, float* __restrict__ y, int rows)
{
    int row = blockIdx.x * 8 + threadIdx.y;
    if (row >= rows) return;
    int lane = threadIdx.x;
    const float4* xr = (const float4*)(x + (size_t)row * DD);
    float4 v0 = xr[lane];
    float4 v1 = xr[lane + 32];
    float s  = v0.x + v0.y + v0.z + v0.w + v1.x + v1.y + v1.z + v1.w;
    float sq = v0.x*v0.x + v0.y*v0.y + v0.z*v0.z + v0.w*v0.w
             + v1.x*v1.x + v1.y*v1.y + v1.z*v1.z + v1.w*v1.w;
#pragma unroll
    for (int o = 16; o > 0; o >>= 1) {
        s  += __shfl_xor_sync(0xffffffffu, s,  o);
        sq += __shfl_xor_sync(0xffffffffu, sq, o);
    }
    float mean = s * (1.f / 256.f);
    float var  = sq * (1.f / 256.f) - mean * mean;
    float inv  = rsqrtf(var + LN_EPS);
    const float4* g4 = (const float4*)g;
    const float4* b4 = (const float4*)b;
    float4* yr = (float4*)(y + (size_t)row * DD);
    float4 gg = g4[lane], bb = b4[lane], o0;
    o0.x = (v0.x - mean) * inv * gg.x + bb.x;
    o0.y = (v0.y - mean) * inv * gg.y + bb.y;
    o0.z = (v0.z - mean) * inv * gg.z + bb.z;
    o0.w = (v0.w - mean) * inv * gg.w + bb.w;
    yr[lane] = o0;
    gg = g4[lane + 32]; bb = b4[lane + 32];
    float4 o1;
    o1.x = (v1.x - mean) * inv * gg.x + bb.x;
    o1.y = (v1.y - mean) * inv * gg.y + bb.y;
    o1.z = (v1.z - mean) * inv * gg.z + bb.z;
    o1.w = (v1.w - mean) * inv * gg.w + bb.w;
    yr[lane + 32] = o1;
}

// ---------------- LayerNorm emitting bf16 hi/lo split ----------------
__global__ void ln_bf16_kernel(const float* __restrict__ x, const float* __restrict__ g,
                               const float* __restrict__ b,
                               __nv_bfloat16* __restrict__ yh, __nv_bfloat16* __restrict__ yl,
                               int rows)
{
    int row = blockIdx.x * 8 + threadIdx.y;
    if (row >= rows) return;
    int lane = threadIdx.x;
    const float4* xr = (const float4*)(x + (size_t)row * DD);
    float4 v0 = xr[lane];
    float4 v1 = xr[lane + 32];
    float s  = v0.x + v0.y + v0.z + v0.w + v1.x + v1.y + v1.z + v1.w;
    float sq = v0.x*v0.x + v0.y*v0.y + v0.z*v0.z + v0.w*v0.w
             + v1.x*v1.x + v1.y*v1.y + v1.z*v1.z + v1.w*v1.w;
#pragma unroll
    for (int o = 16; o > 0; o >>= 1) {
        s  += __shfl_xor_sync(0xffffffffu, s,  o);
        sq += __shfl_xor_sync(0xffffffffu, sq, o);
    }
    float mean = s * (1.f / 256.f);
    float var  = sq * (1.f / 256.f) - mean * mean;
    float inv  = rsqrtf(var + LN_EPS);
    const float4* g4 = (const float4*)g;
    const float4* b4 = (const float4*)b;
    size_t base = (size_t)row * DD;
#pragma unroll
    for (int half = 0; half < 2; half++) {
        float4 v = half ? v1 : v0;
        float4 gg = g4[lane + half * 32], bb = b4[lane + half * 32];
        float4 o;
        o.x = (v.x - mean) * inv * gg.x + bb.x;
        o.y = (v.y - mean) * inv * gg.y + bb.y;
        o.z = (v.z - mean) * inv * gg.z + bb.z;
        o.w = (v.w - mean) * inv * gg.w + bb.w;
        float r0, r1, r2, r3;
        uint2 hp, lp;
        hp.x = pack_bf2(o.x, o.y, &r0, &r1);
        hp.y = pack_bf2(o.z, o.w, &r2, &r3);
        lp.x = pack_bf2_lo(r0, r1);
        lp.y = pack_bf2_lo(r2, r3);
        size_t off = base + half * 128 + lane * 4;
        *(uint2*)(yh + off) = hp;
        *(uint2*)(yl + off) = lp;
    }
}

// ---------------- SIMT GEMM, 64x128 tile (dual via blockIdx.z), fp32 out -------
#define GEMM_AS_PAD 68
#define GEMM_SMEM_FLOATS (64 * GEMM_AS_PAD + 64 * 128)

__global__ __launch_bounds__(256) void gemm256(
    const float* A, const float* W, const float* bias, float* C, int N, int relu,
    const float* A1, const float* W1, const float* bias1, float* C1, int N1)
{
    if (blockIdx.z == 1) { A = A1; W = W1; bias = bias1; C = C1; N = N1; }
    extern __shared__ float sm[];
    float* As = sm;
    float* Bs = sm + 64 * GEMM_AS_PAD;
    const int bn = blockIdx.x * 128;
    const int bm = blockIdx.y * 64;
    const int tid = threadIdx.x;
    const int tx = tid & 15;
    const int ty = tid >> 4;
    float acc[4][8];
#pragma unroll
    for (int i = 0; i < 4; i++)
#pragma unroll
        for (int j = 0; j < 8; j++) acc[i][j] = 0.f;

    for (int k0 = 0; k0 < 256; k0 += 64) {
#pragma unroll
        for (int u = 0; u < 4; u++) {
            int f4 = tid + 256 * u;
            int r = f4 >> 4, c4 = f4 & 15;
            float4 v = *(const float4*)(A + (size_t)(bm + r) * DD + (k0 + c4 * 4));
            As[(c4 * 4 + 0) * GEMM_AS_PAD + r] = v.x;
            As[(c4 * 4 + 1) * GEMM_AS_PAD + r] = v.y;
            As[(c4 * 4 + 2) * GEMM_AS_PAD + r] = v.z;
            As[(c4 * 4 + 3) * GEMM_AS_PAD + r] = v.w;
        }
#pragma unroll
        for (int u = 0; u < 8; u++) {
            int f4 = tid + 256 * u;
            int r = f4 >> 5, c4 = f4 & 31;
            *(float4*)(&Bs[r * 128 + c4 * 4]) =
                *(const float4*)(W + (size_t)(k0 + r) * N + (bn + c4 * 4));
        }
        __syncthreads();
#pragma unroll 8
        for (int k = 0; k < 64; k++) {
            float a[4], bfr[8];
            *(float4*)(a) = *(const float4*)(&As[k * GEMM_AS_PAD + ty * 4]);
            *(float4*)(bfr)     = *(const float4*)(&Bs[k * 128 + tx * 8]);
            *(float4*)(bfr + 4) = *(const float4*)(&Bs[k * 128 + tx * 8 + 4]);
#pragma unroll
            for (int i = 0; i < 4; i++)
#pragma unroll
                for (int j = 0; j < 8; j++)
                    acc[i][j] = fmaf(a[i], bfr[j], acc[i][j]);
        }
        __syncthreads();
    }
    float bv[8];
#pragma unroll
    for (int j = 0; j < 8; j++) bv[j] = bias ? bias[bn + tx * 8 + j] : 0.f;
#pragma unroll
    for (int i = 0; i < 4; i++) {
        float* crow = C + (size_t)(bm + ty * 4 + i) * N + bn + tx * 8;
#pragma unroll
        for (int j = 0; j < 8; j += 4) {
            float4 o;
            o.x = acc[i][j + 0] + bv[j + 0];
            o.y = acc[i][j + 1] + bv[j + 1];
            o.z = acc[i][j + 2] + bv[j + 2];
            o.w = acc[i][j + 3] + bv[j + 3];
            if (relu) {
                o.x = fmaxf(o.x, 0.f); o.y = fmaxf(o.y, 0.f);
                o.z = fmaxf(o.z, 0.f); o.w = fmaxf(o.w, 0.f);
            }
            *(float4*)(crow + j) = o;
        }
    }
}

// ---------------- SIMT GEMM, 32x128 tile, split-bf16 out (q projection) --------
#define QG_AS_PAD 36
#define QG_SMEM_FLOATS (64 * QG_AS_PAD + 64 * 128)

__global__ __launch_bounds__(256) void gemm256_m32(
    const float* __restrict__ A, const float* __restrict__ W,
    __nv_bfloat16* __restrict__ Ch, __nv_bfloat16* __restrict__ Cl, int N)
{
    extern __shared__ float sm[];
    float* As = sm;                      // [64 k][36] transposed, m<32
    float* Bs = sm + 64 * QG_AS_PAD;     // [64][128]
    const int bn = blockIdx.x * 128;
    const int bm = blockIdx.y * 32;
    const int tid = threadIdx.x;
    const int tx = tid & 15;
    const int ty = tid >> 4;
    float acc[2][8];
#pragma unroll
    for (int i = 0; i < 2; i++)
#pragma unroll
        for (int j = 0; j < 8; j++) acc[i][j] = 0.f;

    for (int k0 = 0; k0 < 256; k0 += 64) {
#pragma unroll
        for (int u = 0; u < 2; u++) {
            int f4 = tid + 256 * u;
            int r = f4 >> 4, c4 = f4 & 15;
            float4 v = *(const float4*)(A + (size_t)(bm + r) * DD + (k0 + c4 * 4));
            As[(c4 * 4 + 0) * QG_AS_PAD + r] = v.x;
            As[(c4 * 4 + 1) * QG_AS_PAD + r] = v.y;
            As[(c4 * 4 + 2) * QG_AS_PAD + r] = v.z;
            As[(c4 * 4 + 3) * QG_AS_PAD + r] = v.w;
        }
#pragma unroll
        for (int u = 0; u < 8; u++) {
            int f4 = tid + 256 * u;
            int r = f4 >> 5, c4 = f4 & 31;
            *(float4*)(&Bs[r * 128 + c4 * 4]) =
                *(const float4*)(W + (size_t)(k0 + r) * N + (bn + c4 * 4));
        }
        __syncthreads();
#pragma unroll 8
        for (int k = 0; k < 64; k++) {
            float a0 = As[k * QG_AS_PAD + ty * 2];
            float a1 = As[k * QG_AS_PAD + ty * 2 + 1];
            float bfr[8];
            *(float4*)(bfr)     = *(const float4*)(&Bs[k * 128 + tx * 8]);
            *(float4*)(bfr + 4) = *(const float4*)(&Bs[k * 128 + tx * 8 + 4]);
#pragma unroll
            for (int j = 0; j < 8; j++) {
                acc[0][j] = fmaf(a0, bfr[j], acc[0][j]);
                acc[1][j] = fmaf(a1, bfr[j], acc[1][j]);
            }
        }
        __syncthreads();
    }
#pragma unroll
    for (int i = 0; i < 2; i++) {
        size_t rowo = (size_t)(bm + ty * 2 + i) * N + bn + tx * 8;
#pragma unroll
        for (int j = 0; j < 8; j += 4) {
            float r0, r1, r2, r3;
            uint2 hp, lp;
            hp.x = pack_bf2(acc[i][j + 0], acc[i][j + 1], &r0, &r1);
            hp.y = pack_bf2(acc[i][j + 2], acc[i][j + 3], &r2, &r3);
            lp.x = pack_bf2_lo(r0, r1);
            lp.y = pack_bf2_lo(r2, r3);
            *(uint2*)(Ch + rowo + j) = hp;
            *(uint2*)(Cl + rowo + j) = lp;
        }
    }
}

// ---------------- softmax ----------------
__global__ __launch_bounds__(128) void softmax_kernel(float* __restrict__ attn,
    float* __restrict__ out_attn, int write_mean)
{
    int idx = blockIdx.x * 128 + threadIdx.x;
    int b = idx >> 12, n = idx & 4095;
    float* base = attn + (size_t)b * SH * NTOK + n;
    float vals[SH];
    float mx = -1e30f;
#pragma unroll
    for (int r = 0; r < SH; r++) {
        vals[r] = base[(size_t)r * NTOK];
        mx = fmaxf(mx, vals[r]);
    }
    float s = 0.f;
#pragma unroll
    for (int r = 0; r < SH; r++) { vals[r] = __expf(vals[r] - mx); s += vals[r]; }
    float inv = 1.f / s;
#pragma unroll
    for (int r = 0; r < SH; r++) {
        vals[r] *= inv;
        base[(size_t)r * NTOK] = vals[r];
    }
    if (write_mean) {
#pragma unroll
        for (int i = 0; i < SS; i++) {
            float m = (vals[4*i] + vals[4*i+1] + vals[4*i+2] + vals[4*i+3]) * 0.25f;
            out_attn[((size_t)b * SS + i) * NTOK + n] = m;
        }
    }
}

// ---------------- updates partials + fused last-CTA combine ----------
#define UPD_AS_PAD 260
#define UPD_RS_OFF (256 * 64 + SS * UPD_AS_PAD)
#define UPD_SMEM_FLOATS (UPD_RS_OFF + SS * 64)

__global__ __launch_bounds__(256) void updates_part(const float* __restrict__ attn,
    const float* __restrict__ V, float* __restrict__ updp, float* __restrict__ rsump,
    float* __restrict__ upd, int* __restrict__ cnt)
{
    extern __shared__ float sm[];
    float* vs = sm;
    float* as = sm + 256 * 64;
    float* rs = sm + UPD_RS_OFF;
    __shared__ int s_last;
    const int h = blockIdx.x, b = blockIdx.y, zc = blockIdx.z;
    const int tid = threadIdx.x;
    const int tx = tid & 15, ty = (tid >> 4) & 3, zz = tid >> 6;
    float acc[6][4];
    float srow[6];
#pragma unroll
    for (int i = 0; i < 6; i++) {
        srow[i] = 0.f;
#pragma unroll
        for (int j = 0; j < 4; j++) acc[i][j] = 0.f;
    }

    for (int jt = 0; jt < 4; jt++) {
        int j0 = zc * 1024 + jt * 256;
#pragma unroll
        for (int u = 0; u < 16; u++) {
            int f4 = tid + 256 * u;
            int j = f4 >> 4, d4 = f4 & 15;
            float4 v = *(const float4*)(V + (size_t)(b * NTOK + j0 + j) * DD + h * DHH + d4 * 4);
            *(float4*)(&vs[j * 64 + d4 * 4]) = v;
        }
#pragma unroll
        for (int u = 0; u < 6; u++) {
            int f4 = tid + 256 * u;
            int r = f4 >> 6, c4 = f4 & 63;
            float4 v = *(const float4*)(attn + ((size_t)b * SH + r * HH + h) * NTOK + j0 + c4 * 4);
            *(float4*)(&as[r * UPD_AS_PAD + c4 * 4]) = v;
            srow[u] += v.x + v.y + v.z + v.w;
        }
        __syncthreads();
#pragma unroll 8
        for (int jl = 0; jl < 64; jl++) {
            int j = zz * 64 + jl;
            float4 vv = *(const float4*)(&vs[j * 64 + tx * 4]);
#pragma unroll
            for (int ii = 0; ii < 6; ii++) {
                float a = as[(ty * 6 + ii) * UPD_AS_PAD + j] + EPS;
                acc[ii][0] = fmaf(a, vv.x, acc[ii][0]);
                acc[ii][1] = fmaf(a, vv.y, acc[ii][1]);
                acc[ii][2] = fmaf(a, vv.z, acc[ii][2]);
                acc[ii][3] = fmaf(a, vv.w, acc[ii][3]);
            }
        }
        __syncthreads();
    }
#pragma unroll
    for (int u = 0; u < 6; u++)
        rs[(4 * u + (tid >> 6)) * 64 + (tid & 63)] = srow[u];
    float* red = sm;
#pragma unroll
    for (int ii = 0; ii < 6; ii++)
#pragma unroll
        for (int e = 0; e < 4; e++)
            red[(zz * SS + ty * 6 + ii) * 64 + tx * 4 + e] = acc[ii][e];
    __syncthreads();
    if (tid < SS) {
        float s = 0.f;
        for (int c = 0; c < 64; c++) s += rs[tid * 64 + c];
        rsump[zc * (BB * SH) + b * SH + tid * HH + h] = s;
    }
    for (int t = tid; t < SS * 64; t += 256) {
        int i = t >> 6, d = t & 63;
        float s = red[(0 * SS + i) * 64 + d] + red[(1 * SS + i) * 64 + d]
                + red[(2 * SS + i) * 64 + d] + red[(3 * SS + i) * 64 + d];
        updp[((size_t)zc * ROWS_SL + b * SS + i) * DD + h * DHH + d] = s;
    }

    // last-CTA combine for this (b,h): deterministic fixed-order sum
    __threadfence();
    if (tid == 0) {
        int old = atomicAdd(&cnt[b * HH + h], 1);
        s_last = (old == 3);
        if (s_last) cnt[b * HH + h] = 0;   // self-reset for graph replay
    }
    __syncthreads();
    if (s_last) {
        for (int t = tid; t < SS * 64; t += 256) {
            int i = t >> 6, d = t & 63;
            size_t o = ((size_t)b * SS + i) * DD + h * DHH + d;
            float s = updp[o] + updp[(size_t)ROWS_SL * DD + o]
                    + updp[2 * (size_t)ROWS_SL * DD + o] + updp[3 * (size_t)ROWS_SL * DD + o];
            int ri = b * SH + i * HH + h;
            float r = rsump[ri] + rsump[BB * SH + ri] + rsump[2 * BB * SH + ri]
                    + rsump[3 * BB * SH + ri] + (float)NTOK * EPS;
            upd[o] = s / r;
        }
    }
}

// ---------------- GRU combine ----------------
__global__ void gru_kernel(const float* __restrict__ gi, const float* __restrict__ gh,
                           float* __restrict__ slots)
{
    int row = blockIdx.x;
    int col = threadIdx.x;
    size_t o = (size_t)row * 768;
    float ir = gi[o + col],       iz = gi[o + 256 + col], in_ = gi[o + 512 + col];
    float hr = gh[o + col],       hz = gh[o + 256 + col], hn  = gh[o + 512 + col];
    float hv = slots[(size_t)row * DD + col];
    float r  = 1.f / (1.f + __expf(-(ir + hr)));
    float zz = 1.f / (1.f + __expf(-(iz + hz)));
    float nn = tanhf(in_ + r * hn);
    slots[(size_t)row * DD + col] = (1.f - zz) * nn + zz * hv;
}

__global__ void copy_kernel(const float* __restrict__ src, float* __restrict__ dst, int n)
{
    int i = blockIdx.x * 256 + threadIdx.x;
    if (i < n) dst[i] = src[i];
}

// ---------------- host launch -----------------------------------------------------
extern "C" void kernel_launch(void* const* d_in, const int* in_sizes, int n_in,
                              void* d_out, int out_size)
{
    const float* feat      = (const float*)d_in[0];
    const float* cond      = (const float*)d_in[1];
    const float* pos_ln_g  = (const float*)d_in[2];
    const float* pos_ln_b  = (const float*)d_in[3];
    const float* pos_w1    = (const float*)d_in[4];
    const float* pos_b1    = (const float*)d_in[5];
    const float* pos_w2    = (const float*)d_in[6];
    const float* pos_b2    = (const float*)d_in[7];
    const float* in_ln_g   = (const float*)d_in[8];
    const float* in_ln_b   = (const float*)d_in[9];
    const float* slot_ln_g = (const float*)d_in[10];
    const float* slot_ln_b = (const float*)d_in[11];
    const float* Wq        = (const float*)d_in[12];
    const float* Wk        = (const float*)d_in[13];
    const float* Wv        = (const float*)d_in[14];
    const float* gru_wi    = (const float*)d_in[15];
    const float* gru_wh    = (const float*)d_in[16];
    const float* gru_bi    = (const float*)d_in[17];
    const float* gru_bh    = (const float*)d_in[18];
    float* out = (float*)d_out;
    float* out_attn = out + ROWS_SL * DD;

    float *pA, *pV, *pSlots, *pSn, *pAttn, *pUpdp, *pRsump, *pUpd, *pGi, *pGh;
    int* pCnt;
    __nv_bfloat16 *pKh, *pKl, *pQh, *pQl;
    __nv_bfloat16 *pP0h, *pP0l, *pP1h, *pP1l;
    __nv_bfloat16 *pW1h, *pW1l, *pW2h, *pW2l, *pWkh, *pWkl, *pWvh, *pWvl;
    cudaGetSymbolAddress((void**)&pA, g_bufA);
    cudaGetSymbolAddress((void**)&pKh, g_Kh);
    cudaGetSymbolAddress((void**)&pKl, g_Kl);
    cudaGetSymbolAddress((void**)&pV, g_V);
    cudaGetSymbolAddress((void**)&pP0h, g_P0h);
    cudaGetSymbolAddress((void**)&pP0l, g_P0l);
    cudaGetSymbolAddress((void**)&pP1h, g_P1h);
    cudaGetSymbolAddress((void**)&pP1l, g_P1l);
    cudaGetSymbolAddress((void**)&pW1h, g_W1h);
    cudaGetSymbolAddress((void**)&pW1l, g_W1l);
    cudaGetSymbolAddress((void**)&pW2h, g_W2h);
    cudaGetSymbolAddress((void**)&pW2l, g_W2l);
    cudaGetSymbolAddress((void**)&pWkh, g_Wkh);
    cudaGetSymbolAddress((void**)&pWkl, g_Wkl);
    cudaGetSymbolAddress((void**)&pWvh, g_Wvh);
    cudaGetSymbolAddress((void**)&pWvl, g_Wvl);
    cudaGetSymbolAddress((void**)&pSlots, g_slots);
    cudaGetSymbolAddress((void**)&pSn, g_sn);
    cudaGetSymbolAddress((void**)&pQh, g_qh);
    cudaGetSymbolAddress((void**)&pQl, g_ql);
    cudaGetSymbolAddress((void**)&pAttn, g_attn);
    cudaGetSymbolAddress((void**)&pUpdp, g_updp);
    cudaGetSymbolAddress((void**)&pRsump, g_rsump);
    cudaGetSymbolAddress((void**)&pUpd, g_upd);
    cudaGetSymbolAddress((void**)&pCnt, g_cnt);
    cudaGetSymbolAddress((void**)&pGi, g_gi);
    cudaGetSymbolAddress((void**)&pGh, g_gh);

    const int GEMM_SMEM = GEMM_SMEM_FLOATS * 4;
    const int QG_SMEM   = QG_SMEM_FLOATS * 4;
    const int UPD_SMEM  = UPD_SMEM_FLOATS * 4;
    cudaFuncSetAttribute(gemm256, cudaFuncAttributeMaxDynamicSharedMemorySize, GEMM_SMEM);
    cudaFuncSetAttribute(gemm256_m32, cudaFuncAttributeMaxDynamicSharedMemorySize, QG_SMEM);
    cudaFuncSetAttribute(updates_part, cudaFuncAttributeMaxDynamicSharedMemorySize, UPD_SMEM);
    cudaFuncSetAttribute(gemm_mma, cudaFuncAttributeMaxDynamicSharedMemorySize, TG_SMEM);
    cudaFuncSetAttribute(dots_mma, cudaFuncAttributeMaxDynamicSharedMemorySize, DM_SMEM);

    dim3 lnb(32, 8);

    convert_w4<<<dim3(256, 4), 256>>>(pos_w1, pW1h, pW1l, pos_w2, pW2h, pW2l,
                                      Wk, pWkh, pWkl, Wv, pWvh, pWvl);

    ln_bf16_kernel<<<ROWS_BIG / 8, lnb>>>(feat, pos_ln_g, pos_ln_b, pP0h, pP0l, ROWS_BIG);
    gemm_mma<<<dim3(1, 2048, 1), 256, TG_SMEM>>>(pP0h, pP0l, pW1h, pW1l, pos_b1,
                                                 nullptr, pP1h, pP1l, 1,
                                                 nullptr, nullptr, nullptr);
    gemm_mma<<<dim3(1, 2048, 1), 256, TG_SMEM>>>(pP1h, pP1l, pW2h, pW2l, pos_b2,
                                                 pA, nullptr, nullptr, 0,
                                                 nullptr, nullptr, nullptr);
    ln_bf16_kernel<<<ROWS_BIG / 8, lnb>>>(pA, in_ln_g, in_ln_b, pP0h, pP0l, ROWS_BIG);
    gemm_mma<<<dim3(1, 2048, 2), 256, TG_SMEM>>>(pP0h, pP0l, pWkh, pWkl, nullptr,
                                                 nullptr, pKh, pKl, 0,
                                                 pWvh, pWvl, pV);

    copy_kernel<<<ROWS_SL, 256>>>(cond, pSlots, ROWS_SL * DD);

    for (int it = 0; it < 3; it++) {
        ln_kernel<<<ROWS_SL / 8, lnb>>>(pSlots, slot_ln_g, slot_ln_b, pSn, ROWS_SL);
        gemm256_m32<<<dim3(2, 24), 256, QG_SMEM>>>(pSn, Wq, pQh, pQl, 256);
        dots_mma<<<dim3(16, HH, BB), 256, DM_SMEM>>>(pQh, pQl, pKh, pKl, pAttn);
        softmax_kernel<<<(BB * NTOK) / 128, 128>>>(pAttn, out_attn, (it == 2) ? 1 : 0);
        updates_part<<<dim3(HH, BB, 4), 256, UPD_SMEM>>>(pAttn, pV, pUpdp, pRsump,
                                                         pUpd, pCnt);
        gemm256<<<dim3(6, 12, 2), 256, GEMM_SMEM>>>(pUpd, gru_wi, gru_bi, pGi, 768, 0,
                                                    pSlots, gru_wh, gru_bh, pGh, 768);
        gru_kernel<<<ROWS_SL, 256>>>(pGi, pGh, pSlots);
    }

    copy_kernel<<<ROWS_SL, 256>>>(pSlots, out, ROWS_SL * DD);
}

// round 16
// speedup vs baseline: 1.0364x; 1.0364x over previous
#include <cuda_runtime.h>
#include <cuda_bf16.h>
#include <cstdint>

// ---------------- problem constants ----------------
#define BB   32
#define NTOK 4096
#define SS   24
#define DD   256
#define HH   4
#define DHH  64
#define SH   96              // SS*HH
#define ROWS_BIG (BB*NTOK)   // 131072
#define ROWS_SL  (BB*SS)     // 768
#define EPS   1e-8f
#define LN_EPS 1e-5f
#define SCALE 0.125f         // 64^-0.5

// ---------------- device scratch ----------------
__device__ float g_bufA[ROWS_BIG * DD];
__device__ __nv_bfloat16 g_Kh[ROWS_BIG * DD];
__device__ __nv_bfloat16 g_Kl[ROWS_BIG * DD];
__device__ __nv_bfloat16 g_Vh[ROWS_BIG * DD];
__device__ __nv_bfloat16 g_Vl[ROWS_BIG * DD];
__device__ __nv_bfloat16 g_P0h[ROWS_BIG * DD];
__device__ __nv_bfloat16 g_P0l[ROWS_BIG * DD];
__device__ __nv_bfloat16 g_P1h[ROWS_BIG * DD];
__device__ __nv_bfloat16 g_P1l[ROWS_BIG * DD];
__device__ __nv_bfloat16 g_W1h[DD * DD], g_W1l[DD * DD];
__device__ __nv_bfloat16 g_W2h[DD * DD], g_W2l[DD * DD];
__device__ __nv_bfloat16 g_Wkh[DD * DD], g_Wkl[DD * DD];
__device__ __nv_bfloat16 g_Wvh[DD * DD], g_Wvl[DD * DD];
__device__ float g_slots[ROWS_SL * DD];
__device__ float g_sn[ROWS_SL * DD];
__device__ __nv_bfloat16 g_qh[ROWS_SL * DD];
__device__ __nv_bfloat16 g_ql[ROWS_SL * DD];
__device__ float g_attn[(size_t)BB * SH * NTOK];            // raw scores (pre-softmax)
__device__ __nv_bfloat16 g_ah[(size_t)BB * SH * NTOK];      // (attn+EPS) hi
__device__ __nv_bfloat16 g_al[(size_t)BB * SH * NTOK];      // (attn+EPS) lo
__device__ float g_updp[4 * ROWS_SL * DD];
__device__ float g_rsump[4 * BB * SH];
__device__ float g_upd[ROWS_SL * DD];
__device__ int   g_cnt[BB * HH];          // zero-init; self-resetting
__device__ float g_gi[ROWS_SL * 3 * DD];
__device__ float g_gh[ROWS_SL * 3 * DD];

// ---------------- helpers ----------------
__device__ __forceinline__ uint32_t smem_u32(const void* p) {
    uint32_t a;
    asm("{ .reg .u64 t; cvta.to.shared.u64 t, %1; cvt.u32.u64 %0, t; }" : "=r"(a) : "l"(p));
    return a;
}
__device__ __forceinline__ void cp16(uint32_t dst, const void* src) {
    asm volatile("cp.async.cg.shared.global [%0], [%1], 16;" :: "r"(dst), "l"(src));
}
#define CP_COMMIT() asm volatile("cp.async.commit_group;" ::: "memory")
#define CP_WAIT1()  asm volatile("cp.async.wait_group 1;" ::: "memory")
#define CP_WAIT0()  asm volatile("cp.async.wait_group 0;" ::: "memory")

#define LDSM_X4(R, ADDR) \
    asm volatile("ldmatrix.sync.aligned.m8n8.x4.shared.b16 {%0,%1,%2,%3}, [%4];" \
        : "=r"((R)[0]), "=r"((R)[1]), "=r"((R)[2]), "=r"((R)[3]) : "r"(ADDR))

#define LDSM_X4_T(R, ADDR) \
    asm volatile("ldmatrix.sync.aligned.m8n8.x4.trans.shared.b16 {%0,%1,%2,%3}, [%4];" \
        : "=r"((R)[0]), "=r"((R)[1]), "=r"((R)[2]), "=r"((R)[3]) : "r"(ADDR))

#define MMA16816(C, A, B0, B1) \
    asm volatile("mma.sync.aligned.m16n8k16.row.col.f32.bf16.bf16.f32 " \
        "{%0,%1,%2,%3}, {%4,%5,%6,%7}, {%8,%9}, {%0,%1,%2,%3};" \
        : "+f"((C)[0]), "+f"((C)[1]), "+f"((C)[2]), "+f"((C)[3]) \
        : "r"((A)[0]), "r"((A)[1]), "r"((A)[2]), "r"((A)[3]), "r"(B0), "r"(B1))

__device__ __forceinline__ uint32_t pack_bf2(float a, float b, float* ra, float* rb) {
    __nv_bfloat16 ha = __float2bfloat16(a), hb = __float2bfloat16(b);
    *ra = a - __bfloat162float(ha);
    *rb = b - __bfloat162float(hb);
    return (uint32_t)__bfloat16_as_ushort(ha) | ((uint32_t)__bfloat16_as_ushort(hb) << 16);
}
__device__ __forceinline__ uint32_t pack_bf2_lo(float a, float b) {
    __nv_bfloat16 ha = __float2bfloat16(a), hb = __float2bfloat16(b);
    return (uint32_t)__bfloat16_as_ushort(ha) | ((uint32_t)__bfloat16_as_ushort(hb) << 16);
}
__device__ __forceinline__ float sum_bf2(uint32_t p) {
    __nv_bfloat16 lo = __ushort_as_bfloat16((unsigned short)(p & 0xffff));
    __nv_bfloat16 hi = __ushort_as_bfloat16((unsigned short)(p >> 16));
    return __bfloat162float(lo) + __bfloat162float(hi);
}

// ---------------- mma.sync split-bf16 GEMM, cp.async 2-stage pipelined ----------
#define TG_STAGE 51200
#define TG_SMEM  (2 * TG_STAGE)
#define TG_AL    5120
#define TG_WH    10240
#define TG_WL    30720

__global__ __launch_bounds__(256, 2) void gemm_mma(
    const __nv_bfloat16* __restrict__ Ah, const __nv_bfloat16* __restrict__ Al,
    const __nv_bfloat16* Wh_, const __nv_bfloat16* Wl_,
    const float* __restrict__ bias, float* Cf,
    __nv_bfloat16* Chi, __nv_bfloat16* Clo, int relu,
    const __nv_bfloat16* Wh2, const __nv_bfloat16* Wl2,
    __nv_bfloat16* Chi2, __nv_bfloat16* Clo2)
{
    extern __shared__ char smem[];
    const __nv_bfloat16* Wh = Wh_;
    const __nv_bfloat16* Wl = Wl_;
    if (blockIdx.z == 1) { Wh = Wh2; Wl = Wl2; Cf = nullptr; Chi = Chi2; Clo = Clo2; }

    const int tid = threadIdx.x, lane = tid & 31, wid = tid >> 5;
    const int wm = wid >> 2, wn = wid & 3;
    const int bm = blockIdx.y * 64;
    const uint32_t sb = smem_u32(smem);

    const int r = tid >> 2, q = tid & 3;
    const uint32_t stA = (uint32_t)(r * 80 + q * 16);
    const size_t goA = (size_t)(bm + r) * 512 + q * 16;

    float acc[2][8][4];
#pragma unroll
    for (int i = 0; i < 2; i++)
#pragma unroll
        for (int j = 0; j < 8; j++)
#pragma unroll
            for (int e = 0; e < 4; e++) acc[i][j][e] = 0.f;

    {
        cp16(sb + stA,         (const char*)Ah + goA);
        cp16(sb + TG_AL + stA, (const char*)Al + goA);
#pragma unroll
        for (int u = 0; u < 4; u++) {
            uint32_t rw = (uint32_t)(r + 64 * u);
            uint32_t st = rw * 80 + q * 16;
            size_t go = (size_t)rw * 512 + q * 16;
            cp16(sb + TG_WH + st, (const char*)Wh + go);
            cp16(sb + TG_WL + st, (const char*)Wl + go);
        }
        CP_COMMIT();
    }

    for (int kc = 0; kc < 8; kc++) {
        if (kc < 7) {
            uint32_t d = sb + ((kc + 1) & 1) * TG_STAGE;
            size_t off = (size_t)(kc + 1) * 64;
            cp16(d + stA,         (const char*)Ah + goA + off);
            cp16(d + TG_AL + stA, (const char*)Al + goA + off);
#pragma unroll
            for (int u = 0; u < 4; u++) {
                uint32_t rw = (uint32_t)(r + 64 * u);
                uint32_t st = rw * 80 + q * 16;
                size_t go = (size_t)rw * 512 + q * 16 + off;
                cp16(d + TG_WH + st, (const char*)Wh + go);
                cp16(d + TG_WL + st, (const char*)Wl + go);
            }
            CP_COMMIT();
            CP_WAIT1();
        } else {
            CP_WAIT0();
        }
        __syncthreads();
        uint32_t stg = sb + (kc & 1) * TG_STAGE;
#pragma unroll
        for (int kk = 0; kk < 2; kk++) {
            uint32_t a_h[2][4], a_l[2][4], bfr[4][4];
            uint32_t acol  = kk * 32 + (lane >> 4) * 16;
            uint32_t arow0 = wm * 32 + (lane & 15);
            uint32_t bcol  = kk * 32 + ((lane >> 3) & 1) * 16;
            uint32_t nrowb = wn * 64 + ((lane >> 4) & 1) * 8 + (lane & 7);
            LDSM_X4(a_h[0], stg + arow0 * 80 + acol);
            LDSM_X4(a_h[1], stg + (arow0 + 16) * 80 + acol);
#pragma unroll
            for (int ng = 0; ng < 4; ng++)
                LDSM_X4(bfr[ng], stg + TG_WH + (nrowb + ng * 16) * 80 + bcol);
#pragma unroll
            for (int mt = 0; mt < 2; mt++)
#pragma unroll
                for (int nt = 0; nt < 8; nt++) {
                    int ng = nt >> 1, hb = (nt & 1) * 2;
                    MMA16816(acc[mt][nt], a_h[mt], bfr[ng][hb], bfr[ng][hb + 1]);
                }
            LDSM_X4(a_l[0], stg + TG_AL + arow0 * 80 + acol);
            LDSM_X4(a_l[1], stg + TG_AL + (arow0 + 16) * 80 + acol);
#pragma unroll
            for (int mt = 0; mt < 2; mt++)
#pragma unroll
                for (int nt = 0; nt < 8; nt++) {
                    int ng = nt >> 1, hb = (nt & 1) * 2;
                    MMA16816(acc[mt][nt], a_l[mt], bfr[ng][hb], bfr[ng][hb + 1]);
                }
#pragma unroll
            for (int ng = 0; ng < 4; ng++)
                LDSM_X4(bfr[ng], stg + TG_WL + (nrowb + ng * 16) * 80 + bcol);
#pragma unroll
            for (int mt = 0; mt < 2; mt++)
#pragma unroll
                for (int nt = 0; nt < 8; nt++) {
                    int ng = nt >> 1, hb = (nt & 1) * 2;
                    MMA16816(acc[mt][nt], a_h[mt], bfr[ng][hb], bfr[ng][hb + 1]);
                }
        }
        __syncthreads();
    }

    const int g = lane >> 2, tg = lane & 3;
#pragma unroll
    for (int mt = 0; mt < 2; mt++)
#pragma unroll
        for (int nt = 0; nt < 8; nt++)
#pragma unroll
            for (int half = 0; half < 2; half++) {
                int row = bm + wm * 32 + mt * 16 + g + half * 8;
                int col = wn * 64 + nt * 8 + tg * 2;
                float v0 = acc[mt][nt][half * 2 + 0];
                float v1 = acc[mt][nt][half * 2 + 1];
                if (bias) { v0 += bias[col]; v1 += bias[col + 1]; }
                if (relu) { v0 = fmaxf(v0, 0.f); v1 = fmaxf(v1, 0.f); }
                size_t o = (size_t)row * 256 + col;
                if (Cf) *(float2*)(Cf + o) = make_float2(v0, v1);
                if (Chi) {
                    float r0, r1;
                    uint32_t hp = pack_bf2(v0, v1, &r0, &r1);
                    *(uint32_t*)(Chi + o) = hp;
                    *(uint32_t*)(Clo + o) = pack_bf2_lo(r0, r1);
                }
            }
}

// ---------------- dots via mma: attn[b,i*4+h,n] = SCALE * q.K^T (split bf16) -----
#define DM_QH 0
#define DM_QL 4608
#define DM_KH 9216
#define DM_KL 46080
#define DM_SMEM 82944

__global__ __launch_bounds__(256, 2) void dots_mma(
    const __nv_bfloat16* __restrict__ qh, const __nv_bfloat16* __restrict__ ql,
    const __nv_bfloat16* __restrict__ Kh, const __nv_bfloat16* __restrict__ Kl,
    float* __restrict__ attn)
{
    extern __shared__ char smem[];
    const int b = blockIdx.z, h = blockIdx.y, n0 = blockIdx.x * 256;
    const int tid = threadIdx.x, lane = tid & 31, wn = tid >> 5;
    const uint32_t sb = smem_u32(smem);

#pragma unroll
    for (int u = 0; u < 8; u++) {
        int idx = u * 256 + tid;
        int row = idx >> 3, qq = idx & 7;
        uint32_t st = (uint32_t)(row * 144 + qq * 16);
        size_t go = ((size_t)(b * NTOK + n0 + row) * 256 + h * DHH) * 2 + qq * 16;
        cp16(sb + DM_KH + st, (const char*)Kh + go);
        cp16(sb + DM_KL + st, (const char*)Kl + go);
    }
    CP_COMMIT();
    {
        int row = tid >> 3, qq = tid & 7;
        uint32_t st = (uint32_t)(row * 144 + qq * 16);
        if (row < SS) {
            size_t go = ((size_t)(b * SS + row) * 256 + h * DHH) * 2 + qq * 16;
            *(uint4*)(smem + DM_QH + st) = *(const uint4*)((const char*)qh + go);
            *(uint4*)(smem + DM_QL + st) = *(const uint4*)((const char*)ql + go);
        } else {
            uint4 z = make_uint4(0, 0, 0, 0);
            *(uint4*)(smem + DM_QH + st) = z;
            *(uint4*)(smem + DM_QL + st) = z;
        }
    }
    CP_WAIT0();
    __syncthreads();

    float acc[2][4][4];
#pragma unroll
    for (int i = 0; i < 2; i++)
#pragma unroll
        for (int j = 0; j < 4; j++)
#pragma unroll
            for (int e = 0; e < 4; e++) acc[i][j][e] = 0.f;

#pragma unroll
    for (int ks = 0; ks < 4; ks++) {
        uint32_t a_h[2][4], a_l[2][4], bfr[2][4];
        uint32_t acol = ks * 32 + (lane >> 4) * 16;
        uint32_t arow = (uint32_t)(lane & 15);
        uint32_t bcol = ks * 32 + ((lane >> 3) & 1) * 16;
        uint32_t nrow = (uint32_t)(wn * 32 + ((lane >> 4) & 1) * 8 + (lane & 7));
        LDSM_X4(a_h[0], sb + DM_QH + arow * 144 + acol);
        LDSM_X4(a_h[1], sb + DM_QH + (arow + 16) * 144 + acol);
        LDSM_X4(bfr[0], sb + DM_KH + nrow * 144 + bcol);
        LDSM_X4(bfr[1], sb + DM_KH + (nrow + 16) * 144 + bcol);
#pragma unroll
        for (int mt = 0; mt < 2; mt++)
#pragma unroll
            for (int nt = 0; nt < 4; nt++) {
                int ng = nt >> 1, hb = (nt & 1) * 2;
                MMA16816(acc[mt][nt], a_h[mt], bfr[ng][hb], bfr[ng][hb + 1]);
            }
        LDSM_X4(a_l[0], sb + DM_QL + arow * 144 + acol);
        LDSM_X4(a_l[1], sb + DM_QL + (arow + 16) * 144 + acol);
#pragma unroll
        for (int mt = 0; mt < 2; mt++)
#pragma unroll
            for (int nt = 0; nt < 4; nt++) {
                int ng = nt >> 1, hb = (nt & 1) * 2;
                MMA16816(acc[mt][nt], a_l[mt], bfr[ng][hb], bfr[ng][hb + 1]);
            }
        LDSM_X4(bfr[0], sb + DM_KL + nrow * 144 + bcol);
        LDSM_X4(bfr[1], sb + DM_KL + (nrow + 16) * 144 + bcol);
#pragma unroll
        for (int mt = 0; mt < 2; mt++)
#pragma unroll
            for (int nt = 0; nt < 4; nt++) {
                int ng = nt >> 1, hb = (nt & 1) * 2;
                MMA16816(acc[mt][nt], a_h[mt], bfr[ng][hb], bfr[ng][hb + 1]);
            }
    }

    const int g = lane >> 2, tg = lane & 3;
#pragma unroll
    for (int mt = 0; mt < 2; mt++)
#pragma unroll
        for (int nt = 0; nt < 4; nt++)
#pragma unroll
            for (int half = 0; half < 2; half++) {
                if (mt == 1 && half == 1) continue;
                int row = mt * 16 + g + half * 8;
                int col = n0 + wn * 32 + nt * 8 + tg * 2;
                float v0 = acc[mt][nt][half * 2 + 0] * SCALE;
                float v1 = acc[mt][nt][half * 2 + 1] * SCALE;
                *(float2*)(attn + ((size_t)b * SH + row * HH + h) * NTOK + col)
                    = make_float2(v0, v1);
            }
}

// ---------------- updates via mma: updT[d, i] = V^T @ (attn+EPS)^T ----------------
// Per (h, b, zc): M=64 (d), N=32 (i, 24 real), K=1024 (j) in 4 chunks of 256.
// V staged [256 j][64 d] bf16 (128B data + 16 pad = 144 stride), A-frag via .trans.
// attn staged [32 i][256 j] bf16 (512B data + 16 pad = 528 stride), B-frag non-trans.
#define UM_VH 0
#define UM_VL 36864
#define UM_AH 73728
#define UM_AL (UM_AH + 32 * 528)
#define UM_SMEM (UM_AL + 32 * 528)      // 107520 B

__global__ __launch_bounds__(256, 2) void updates_mma(
    const __nv_bfloat16* __restrict__ ah, const __nv_bfloat16* __restrict__ al,
    const __nv_bfloat16* __restrict__ Vh, const __nv_bfloat16* __restrict__ Vl,
    float* __restrict__ updp, float* __restrict__ rsump,
    float* __restrict__ upd, int* __restrict__ cnt)
{
    extern __shared__ char smem[];
    __shared__ int s_last;
    const int h = blockIdx.x, b = blockIdx.y, zc = blockIdx.z;
    const int tid = threadIdx.x, lane = tid & 31, wid = tid >> 5;
    const int wm = wid >> 1, wn2 = wid & 1;      // 4 m-groups x 2 n-groups
    const uint32_t sb = smem_u32(smem);

    // zero pad rows 24..31 of attn tiles (never overwritten)
    for (int idx = tid; idx < 8 * 33; idx += 256) {
        int row = 24 + (idx / 33), qq = idx % 33;
        uint4 z = make_uint4(0, 0, 0, 0);
        *(uint4*)(smem + UM_AH + row * 528 + qq * 16) = z;
        *(uint4*)(smem + UM_AL + row * 528 + qq * 16) = z;
    }

    float acc[2][4];
#pragma unroll
    for (int i = 0; i < 2; i++)
#pragma unroll
        for (int e = 0; e < 4; e++) acc[i][e] = 0.f;
    float rsum = 0.f;
    const int rrow = tid >> 3;          // rsum row (0..31)
    const int rq0  = (tid & 7) * 4;     // 4 uint4 per thread per chunk

    for (int c = 0; c < 4; c++) {
        int j0 = zc * 1024 + c * 256;
        __syncthreads();   // protect smem from previous chunk's readers
        // V tiles: 256 rows x 8 quads
#pragma unroll
        for (int u = 0; u < 8; u++) {
            int idx = u * 256 + tid;
            int row = idx >> 3, qq = idx & 7;
            uint32_t st = (uint32_t)(row * 144 + qq * 16);
            size_t go = ((size_t)(b * NTOK + j0 + row) * 256 + h * DHH) * 2 + qq * 16;
            cp16(sb + UM_VH + st, (const char*)Vh + go);
            cp16(sb + UM_VL + st, (const char*)Vl + go);
        }
        // attn tiles: 24 rows x 32 quads
#pragma unroll
        for (int u = 0; u < 3; u++) {
            int idx = u * 256 + tid;
            int row = idx >> 5, qq = idx & 31;
            uint32_t st = (uint32_t)(row * 528 + qq * 16);
            size_t go = ((size_t)(b * SH + row * HH + h) * NTOK + j0) * 2 + qq * 16;
            cp16(sb + UM_AH + st, (const char*)ah + go);
            cp16(sb + UM_AL + st, (const char*)al + go);
        }
        CP_COMMIT();
        CP_WAIT0();
        __syncthreads();

        // rsum partials from staged attn (exact fp32 sum of hi+lo)
        if (rrow < SS) {
#pragma unroll
            for (int u = 0; u < 4; u++) {
                uint4 hv = *(uint4*)(smem + UM_AH + rrow * 528 + (rq0 + u) * 16);
                uint4 lv = *(uint4*)(smem + UM_AL + rrow * 528 + (rq0 + u) * 16);
                rsum += sum_bf2(hv.x) + sum_bf2(hv.y) + sum_bf2(hv.z) + sum_bf2(hv.w);
                rsum += sum_bf2(lv.x) + sum_bf2(lv.y) + sum_bf2(lv.z) + sum_bf2(lv.w);
            }
        }

        // MMA over 16 k16 steps
#pragma unroll 4
        for (int ks = 0; ks < 16; ks++) {
            uint32_t a_h[4], a_l[4], b_h[4], b_l[4];
            uint32_t krow = (uint32_t)(ks * 16 + (lane & 7) + ((lane >> 4) & 1) * 8);
            uint32_t acb  = (uint32_t)(wm * 32 + ((lane >> 3) & 1) * 16);
            uint32_t nrow = (uint32_t)(wn2 * 16 + ((lane >> 4) & 1) * 8 + (lane & 7));
            uint32_t bcb  = (uint32_t)(ks * 32 + ((lane >> 3) & 1) * 16);
            LDSM_X4_T(a_h, sb + UM_VH + krow * 144 + acb);
            LDSM_X4(b_h, sb + UM_AH + nrow * 528 + bcb);
#pragma unroll
            for (int nf = 0; nf < 2; nf++)
                MMA16816(acc[nf], a_h, b_h[nf * 2], b_h[nf * 2 + 1]);
            LDSM_X4_T(a_l, sb + UM_VL + krow * 144 + acb);
#pragma unroll
            for (int nf = 0; nf < 2; nf++)
                MMA16816(acc[nf], a_l, b_h[nf * 2], b_h[nf * 2 + 1]);
            LDSM_X4(b_l, sb + UM_AL + nrow * 528 + bcb);
#pragma unroll
            for (int nf = 0; nf < 2; nf++)
                MMA16816(acc[nf], a_h, b_l[nf * 2], b_l[nf * 2 + 1]);
        }
    }

    // rsum reduce across 8 threads per row
#pragma unroll
    for (int o = 4; o > 0; o >>= 1)
        rsum += __shfl_down_sync(0xffffffffu, rsum, o, 8);
    if ((tid & 7) == 0 && rrow < SS)
        rsump[zc * (BB * SH) + b * SH + rrow * HH + h] = rsum;

    // epilogue: C'[d][i] -> updp[zc][b*24+i][h*64+d]
    const int g = lane >> 2, tg = lane & 3;
#pragma unroll
    for (int nf = 0; nf < 2; nf++)
#pragma unroll
        for (int hf = 0; hf < 2; hf++) {
            int d = wm * 16 + g + hf * 8;
            int i0 = wn2 * 16 + nf * 8 + tg * 2;
            if (i0 < SS) {
                float v0 = acc[nf][hf * 2 + 0];
                float v1 = acc[nf][hf * 2 + 1];
                updp[((size_t)zc * ROWS_SL + b * SS + i0) * DD + h * DHH + d] = v0;
                updp[((size_t)zc * ROWS_SL + b * SS + i0 + 1) * DD + h * DHH + d] = v1;
            }
        }

    // last-CTA combine for this (b,h)
    __threadfence();
    if (tid == 0) {
        int old = atomicAdd(&cnt[b * HH + h], 1);
        s_last = (old == 3);
        if (s_last) cnt[b * HH + h] = 0;
    }
    __syncthreads();
    if (s_last) {
        for (int t = tid; t < SS * 64; t += 256) {
            int i = t >> 6, d = t & 63;
            size_t o = ((size_t)b * SS + i) * DD + h * DHH + d;
            float s = updp[o] + updp[(size_t)ROWS_SL * DD + o]
                    + updp[2 * (size_t)ROWS_SL * DD + o] + updp[3 * (size_t)ROWS_SL * DD + o];
            int ri = b * SH + i * HH + h;
            float r = rsump[ri] + rsump[BB * SH + ri] + rsump[2 * BB * SH + ri]
                    + rsump[3 * BB * SH + ri];   // EPS already baked into values
            upd[o] = s / r;
        }
    }
}

// ---------------- W transpose + bf16 split (4 weights, one launch) ----------------
__global__ void convert_w4(
    const float* __restrict__ W0, __nv_bfloat16* __restrict__ H0, __nv_bfloat16* __restrict__ L0,
    const float* __restrict__ W1, __nv_bfloat16* __restrict__ H1, __nv_bfloat16* __restrict__ L1,
    const float* __restrict__ W2, __nv_bfloat16* __restrict__ H2, __nv_bfloat16* __restrict__ L2,
    const float* __restrict__ W3, __nv_bfloat16* __restrict__ H3, __nv_bfloat16* __restrict__ L3)
{
    const float* W; __nv_bfloat16 *Hh, *Hl;
    switch (blockIdx.y) {
        case 0: W = W0; Hh = H0; Hl = L0; break;
        case 1: W = W1; Hh = H1; Hl = L1; break;
        case 2: W = W2; Hh = H2; Hl = L2; break;
        default: W = W3; Hh = H3; Hl = L3; break;
    }
    int k = blockIdx.x;
    int n = threadIdx.x;
    float v = W[k * DD + n];
    __nv_bfloat16 h = __float2bfloat16(v);
    Hh[n * DD + k] = h;
    Hl[n * DD + k] = __float2bfloat16(v - __bfloat162float(h));
}

// ---------------- LayerNorm (fp32 out, slots path) ----------------
__global__ void ln_kernel(const float* __restrict__ x, const float* __restrict__ g,
                          const float* __restrict__ b, float* __restrict__ y, int rows)
{
    int row = blockIdx.x * 8 + threadIdx.y;
    if (row >= rows) return;
    int lane = threadIdx.x;
    const float4* xr = (const float4*)(x + (size_t)row * DD);
    float4 v0 = xr[lane];
    float4 v1 = xr[lane + 32];
    float s  = v0.x + v0.y + v0.z + v0.w + v1.x + v1.y + v1.z + v1.w;
    float sq = v0.x*v0.x + v0.y*v0.y + v0.z*v0.z + v0.w*v0.w
             + v1.x*v1.x + v1.y*v1.y + v1.z*v1.z + v1.w*v1.w;
#pragma unroll
    for (int o = 16; o > 0; o >>= 1) {
        s  += __shfl_xor_sync(0xffffffffu, s,  o);
        sq += __shfl_xor_sync(0xffffffffu, sq, o);
    }
    float mean = s * (1.f / 256.f);
    float var  = sq * (1.f / 256.f) - mean * mean;
    float inv  = rsqrtf(var + LN_EPS);
    const float4* g4 = (const float4*)g;
    const float4* b4 = (const float4*)b;
    float4* yr = (float4*)(y + (size_t)row * DD);
    float4 gg = g4[lane], bb = b4[lane], o0;
    o0.x = (v0.x - mean) * inv * gg.x + bb.x;
    o0.y = (v0.y - mean) * inv * gg.y + bb.y;
    o0.z = (v0.z - mean) * inv * gg.z + bb.z;
    o0.w = (v0.w - mean) * inv * gg.w + bb.w;
    yr[lane] = o0;
    gg = g4[lane + 32]; bb = b4[lane + 32];
    float4 o1;
    o1.x = (v1.x - mean) * inv * gg.x + bb.x;
    o1.y = (v1.y - mean) * inv * gg.y + bb.y;
    o1.z = (v1.z - mean) * inv * gg.z + bb.z;
    o1.w = (v1.w - mean) * inv * gg.w + bb.w;
    yr[lane + 32] = o1;
}

// ---------------- LayerNorm emitting bf16 hi/lo split ----------------
__global__ void ln_bf16_kernel(const float* __restrict__ x, const float* __restrict__ g,
                               const float* __restrict__ b,
                               __nv_bfloat16* __restrict__ yh, __nv_bfloat16* __restrict__ yl,
                               int rows)
{
    int row = blockIdx.x * 8 + threadIdx.y;
    if (row >= rows) return;
    int lane = threadIdx.x;
    const float4* xr = (const float4*)(x + (size_t)row * DD);
    float4 v0 = xr[lane];
    float4 v1 = xr[lane + 32];
    float s  = v0.x + v0.y + v0.z + v0.w + v1.x + v1.y + v1.z + v1.w;
    float sq = v0.x*v0.x + v0.y*v0.y + v0.z*v0.z + v0.w*v0.w
             + v1.x*v1.x + v1.y*v1.y + v1.z*v1.z + v1.w*v1.w;
#pragma unroll
    for (int o = 16; o > 0; o >>= 1) {
        s  += __shfl_xor_sync(0xffffffffu, s,  o);
        sq += __shfl_xor_sync(0xffffffffu, sq, o);
    }
    float mean = s * (1.f / 256.f);
    float var  = sq * (1.f / 256.f) - mean * mean;
    float inv  = rsqrtf(var + LN_EPS);
    const float4* g4 = (const float4*)g;
    const float4* b4 = (const float4*)b;
    size_t base = (size_t)row * DD;
#pragma unroll
    for (int half = 0; half < 2; half++) {
        float4 v = half ? v1 : v0;
        float4 gg = g4[lane + half * 32], bb = b4[lane + half * 32];
        float4 o;
        o.x = (v.x - mean) * inv * gg.x + bb.x;
        o.y = (v.y - mean) * inv * gg.y + bb.y;
        o.z = (v.z - mean) * inv * gg.z + bb.z;
        o.w = (v.w - mean) * inv * gg.w + bb.w;
        float r0, r1, r2, r3;
        uint2 hp, lp;
        hp.x = pack_bf2(o.x, o.y, &r0, &r1);
        hp.y = pack_bf2(o.z, o.w, &r2, &r3);
        lp.x = pack_bf2_lo(r0, r1);
        lp.y = pack_bf2_lo(r2, r3);
        size_t off = base + half * 128 + lane * 4;
        *(uint2*)(yh + off) = hp;
        *(uint2*)(yl + off) = lp;
    }
}

// ---------------- SIMT GEMM, 64x128 tile (dual via blockIdx.z), fp32 out -------
#define GEMM_AS_PAD 68
#define GEMM_SMEM_FLOATS (64 * GEMM_AS_PAD + 64 * 128)

__global__ __launch_bounds__(256) void gemm256(
    const float* A, const float* W, const float* bias, float* C, int N, int relu,
    const float* A1, const float* W1, const float* bias1, float* C1, int N1)
{
    if (blockIdx.z == 1) { A = A1; W = W1; bias = bias1; C = C1; N = N1; }
    extern __shared__ float sm[];
    float* As = sm;
    float* Bs = sm + 64 * GEMM_AS_PAD;
    const int bn = blockIdx.x * 128;
    const int bm = blockIdx.y * 64;
    const int tid = threadIdx.x;
    const int tx = tid & 15;
    const int ty = tid >> 4;
    float acc[4][8];
#pragma unroll
    for (int i = 0; i < 4; i++)
#pragma unroll
        for (int j = 0; j < 8; j++) acc[i][j] = 0.f;

    for (int k0 = 0; k0 < 256; k0 += 64) {
#pragma unroll
        for (int u = 0; u < 4; u++) {
            int f4 = tid + 256 * u;
            int r = f4 >> 4, c4 = f4 & 15;
            float4 v = *(const float4*)(A + (size_t)(bm + r) * DD + (k0 + c4 * 4));
            As[(c4 * 4 + 0) * GEMM_AS_PAD + r] = v.x;
            As[(c4 * 4 + 1) * GEMM_AS_PAD + r] = v.y;
            As[(c4 * 4 + 2) * GEMM_AS_PAD + r] = v.z;
            As[(c4 * 4 + 3) * GEMM_AS_PAD + r] = v.w;
        }
#pragma unroll
        for (int u = 0; u < 8; u++) {
            int f4 = tid + 256 * u;
            int r = f4 >> 5, c4 = f4 & 31;
            *(float4*)(&Bs[r * 128 + c4 * 4]) =
                *(const float4*)(W + (size_t)(k0 + r) * N + (bn + c4 * 4));
        }
        __syncthreads();
#pragma unroll 8
        for (int k = 0; k < 64; k++) {
            float a[4], bfr[8];
            *(float4*)(a) = *(const float4*)(&As[k * GEMM_AS_PAD + ty * 4]);
            *(float4*)(bfr)     = *(const float4*)(&Bs[k * 128 + tx * 8]);
            *(float4*)(bfr + 4) = *(const float4*)(&Bs[k * 128 + tx * 8 + 4]);
#pragma unroll
            for (int i = 0; i < 4; i++)
#pragma unroll
                for (int j = 0; j < 8; j++)
                    acc[i][j] = fmaf(a[i], bfr[j], acc[i][j]);
        }
        __syncthreads();
    }
    float bv[8];
#pragma unroll
    for (int j = 0; j < 8; j++) bv[j] = bias ? bias[bn + tx * 8 + j] : 0.f;
#pragma unroll
    for (int i = 0; i < 4; i++) {
        float* crow = C + (size_t)(bm + ty * 4 + i) * N + bn + tx * 8;
#pragma unroll
        for (int j = 0; j < 8; j += 4) {
            float4 o;
            o.x = acc[i][j + 0] + bv[j + 0];
            o.y = acc[i][j + 1] + bv[j + 1];
            o.z = acc[i][j + 2] + bv[j + 2];
            o.w = acc[i][j + 3] + bv[j + 3];
            if (relu) {
                o.x = fmaxf(o.x, 0.f); o.y = fmaxf(o.y, 0.f);
                o.z = fmaxf(o.z, 0.f); o.w = fmaxf(o.w, 0.f);
            }
            *(float4*)(crow + j) = o;
        }
    }
}

// ---------------- SIMT GEMM, 32x128 tile, split-bf16 out (q projection) --------
#define QG_AS_PAD 36
#define QG_SMEM_FLOATS (64 * QG_AS_PAD + 64 * 128)

__global__ __launch_bounds__(256) void gemm256_m32(
    const float* __restrict__ A, const float* __restrict__ W,
    __nv_bfloat16* __restrict__ Ch, __nv_bfloat16* __restrict__ Cl, int N)
{
    extern __shared__ float sm[];
    float* As = sm;
    float* Bs = sm + 64 * QG_AS_PAD;
    const int bn = blockIdx.x * 128;
    const int bm = blockIdx.y * 32;
    const int tid = threadIdx.x;
    const int tx = tid & 15;
    const int ty = tid >> 4;
    float acc[2][8];
#pragma unroll
    for (int i = 0; i < 2; i++)
#pragma unroll
        for (int j = 0; j < 8; j++) acc[i][j] = 0.f;

    for (int k0 = 0; k0 < 256; k0 += 64) {
#pragma unroll
        for (int u = 0; u < 2; u++) {
            int f4 = tid + 256 * u;
            int r = f4 >> 4, c4 = f4 & 15;
            float4 v = *(const float4*)(A + (size_t)(bm + r) * DD + (k0 + c4 * 4));
            As[(c4 * 4 + 0) * QG_AS_PAD + r] = v.x;
            As[(c4 * 4 + 1) * QG_AS_PAD + r] = v.y;
            As[(c4 * 4 + 2) * QG_AS_PAD + r] = v.z;
            As[(c4 * 4 + 3) * QG_AS_PAD + r] = v.w;
        }
#pragma unroll
        for (int u = 0; u < 8; u++) {
            int f4 = tid + 256 * u;
            int r = f4 >> 5, c4 = f4 & 31;
            *(float4*)(&Bs[r * 128 + c4 * 4]) =
                *(const float4*)(W + (size_t)(k0 + r) * N + (bn + c4 * 4));
        }
        __syncthreads();
#pragma unroll 8
        for (int k = 0; k < 64; k++) {
            float a0 = As[k * QG_AS_PAD + ty * 2];
            float a1 = As[k * QG_AS_PAD + ty * 2 + 1];
            float bfr[8];
            *(float4*)(bfr)     = *(const float4*)(&Bs[k * 128 + tx * 8]);
            *(float4*)(bfr + 4) = *(const float4*)(&Bs[k * 128 + tx * 8 + 4]);
#pragma unroll
            for (int j = 0; j < 8; j++) {
                acc[0][j] = fmaf(a0, bfr[j], acc[0][j]);
                acc[1][j] = fmaf(a1, bfr[j], acc[1][j]);
            }
        }
        __syncthreads();
    }
#pragma unroll
    for (int i = 0; i < 2; i++) {
        size_t rowo = (size_t)(bm + ty * 2 + i) * N + bn + tx * 8;
#pragma unroll
        for (int j = 0; j < 8; j += 4) {
            float r0, r1, r2, r3;
            uint2 hp, lp;
            hp.x = pack_bf2(acc[i][j + 0], acc[i][j + 1], &r0, &r1);
            hp.y = pack_bf2(acc[i][j + 2], acc[i][j + 3], &r2, &r3);
            lp.x = pack_bf2_lo(r0, r1);
            lp.y = pack_bf2_lo(r2, r3);
            *(uint2*)(Ch + rowo + j) = hp;
            *(uint2*)(Cl + rowo + j) = lp;
        }
    }
}

// ---------------- softmax: fp32 scores -> (attn+EPS) bf16 hi/lo + optional mean ----
__global__ __launch_bounds__(128) void softmax_kernel(const float* __restrict__ attn,
    __nv_bfloat16* __restrict__ oh, __nv_bfloat16* __restrict__ ol,
    float* __restrict__ out_attn, int write_mean)
{
    int idx = blockIdx.x * 128 + threadIdx.x;
    int b = idx >> 12, n = idx & 4095;
    const float* base = attn + (size_t)b * SH * NTOK + n;
    float vals[SH];
    float mx = -1e30f;
#pragma unroll
    for (int r = 0; r < SH; r++) {
        vals[r] = base[(size_t)r * NTOK];
        mx = fmaxf(mx, vals[r]);
    }
    float s = 0.f;
#pragma unroll
    for (int r = 0; r < SH; r++) { vals[r] = __expf(vals[r] - mx); s += vals[r]; }
    float inv = 1.f / s;
    size_t obase = (size_t)b * SH * NTOK + n;
#pragma unroll
    for (int r = 0; r < SH; r++) {
        vals[r] *= inv;
        float t = vals[r] + EPS;
        __nv_bfloat16 hi = __float2bfloat16(t);
        __nv_bfloat16 lo = __float2bfloat16(t - __bfloat162float(hi));
        oh[obase + (size_t)r * NTOK] = hi;
        ol[obase + (size_t)r * NTOK] = lo;
    }
    if (write_mean) {
#pragma unroll
        for (int i = 0; i < SS; i++) {
            float m = (vals[4*i] + vals[4*i+1] + vals[4*i+2] + vals[4*i+3]) * 0.25f;
            out_attn[((size_t)b * SS + i) * NTOK + n] = m;
        }
    }
}

// ---------------- GRU combine ----------------
__global__ void gru_kernel(const float* __restrict__ gi, const float* __restrict__ gh,
                           float* __restrict__ slots)
{
    int row = blockIdx.x;
    int col = threadIdx.x;
    size_t o = (size_t)row * 768;
    float ir = gi[o + col],       iz = gi[o + 256 + col], in_ = gi[o + 512 + col];
    float hr = gh[o + col],       hz = gh[o + 256 + col], hn  = gh[o + 512 + col];
    float hv = slots[(size_t)row * DD + col];
    float r  = 1.f / (1.f + __expf(-(ir + hr)));
    float zz = 1.f / (1.f + __expf(-(iz + hz)));
    float nn = tanhf(in_ + r * hn);
    slots[(size_t)row * DD + col] = (1.f - zz) * nn + zz * hv;
}

__global__ void copy_kernel(const float* __restrict__ src, float* __restrict__ dst, int n)
{
    int i = blockIdx.x * 256 + threadIdx.x;
    if (i < n) dst[i] = src[i];
}

// ---------------- host launch -----------------------------------------------------
extern "C" void kernel_launch(void* const* d_in, const int* in_sizes, int n_in,
                              void* d_out, int out_size)
{
    const float* feat      = (const float*)d_in[0];
    const float* cond      = (const float*)d_in[1];
    const float* pos_ln_g  = (const float*)d_in[2];
    const float* pos_ln_b  = (const float*)d_in[3];
    const float* pos_w1    = (const float*)d_in[4];
    const float* pos_b1    = (const float*)d_in[5];
    const float* pos_w2    = (const float*)d_in[6];
    const float* pos_b2    = (const float*)d_in[7];
    const float* in_ln_g   = (const float*)d_in[8];
    const float* in_ln_b   = (const float*)d_in[9];
    const float* slot_ln_g = (const float*)d_in[10];
    const float* slot_ln_b = (const float*)d_in[11];
    const float* Wq        = (const float*)d_in[12];
    const float* Wk        = (const float*)d_in[13];
    const float* Wv        = (const float*)d_in[14];
    const float* gru_wi    = (const float*)d_in[15];
    const float* gru_wh    = (const float*)d_in[16];
    const float* gru_bi    = (const float*)d_in[17];
    const float* gru_bh    = (const float*)d_in[18];
    float* out = (float*)d_out;
    float* out_attn = out + ROWS_SL * DD;

    float *pA, *pSlots, *pSn, *pAttn, *pUpdp, *pRsump, *pUpd, *pGi, *pGh;
    int* pCnt;
    __nv_bfloat16 *pKh, *pKl, *pVh, *pVl, *pQh, *pQl, *pAh, *pAl;
    __nv_bfloat16 *pP0h, *pP0l, *pP1h, *pP1l;
    __nv_bfloat16 *pW1h, *pW1l, *pW2h, *pW2l, *pWkh, *pWkl, *pWvh, *pWvl;
    cudaGetSymbolAddress((void**)&pA, g_bufA);
    cudaGetSymbolAddress((void**)&pKh, g_Kh);
    cudaGetSymbolAddress((void**)&pKl, g_Kl);
    cudaGetSymbolAddress((void**)&pVh, g_Vh);
    cudaGetSymbolAddress((void**)&pVl, g_Vl);
    cudaGetSymbolAddress((void**)&pP0h, g_P0h);
    cudaGetSymbolAddress((void**)&pP0l, g_P0l);
    cudaGetSymbolAddress((void**)&pP1h, g_P1h);
    cudaGetSymbolAddress((void**)&pP1l, g_P1l);
    cudaGetSymbolAddress((void**)&pW1h, g_W1h);
    cudaGetSymbolAddress((void**)&pW1l, g_W1l);
    cudaGetSymbolAddress((void**)&pW2h, g_W2h);
    cudaGetSymbolAddress((void**)&pW2l, g_W2l);
    cudaGetSymbolAddress((void**)&pWkh, g_Wkh);
    cudaGetSymbolAddress((void**)&pWkl, g_Wkl);
    cudaGetSymbolAddress((void**)&pWvh, g_Wvh);
    cudaGetSymbolAddress((void**)&pWvl, g_Wvl);
    cudaGetSymbolAddress((void**)&pSlots, g_slots);
    cudaGetSymbolAddress((void**)&pSn, g_sn);
    cudaGetSymbolAddress((void**)&pQh, g_qh);
    cudaGetSymbolAddress((void**)&pQl, g_ql);
    cudaGetSymbolAddress((void**)&pAttn, g_attn);
    cudaGetSymbolAddress((void**)&pAh, g_ah);
    cudaGetSymbolAddress((void**)&pAl, g_al);
    cudaGetSymbolAddress((void**)&pUpdp, g_updp);
    cudaGetSymbolAddress((void**)&pRsump, g_rsump);
    cudaGetSymbolAddress((void**)&pUpd, g_upd);
    cudaGetSymbolAddress((void**)&pCnt, g_cnt);
    cudaGetSymbolAddress((void**)&pGi, g_gi);
    cudaGetSymbolAddress((void**)&pGh, g_gh);

    const int GEMM_SMEM = GEMM_SMEM_FLOATS * 4;
    const int QG_SMEM   = QG_SMEM_FLOATS * 4;
    cudaFuncSetAttribute(gemm256, cudaFuncAttributeMaxDynamicSharedMemorySize, GEMM_SMEM);
    cudaFuncSetAttribute(gemm256_m32, cudaFuncAttributeMaxDynamicSharedMemorySize, QG_SMEM);
    cudaFuncSetAttribute(gemm_mma, cudaFuncAttributeMaxDynamicSharedMemorySize, TG_SMEM);
    cudaFuncSetAttribute(dots_mma, cudaFuncAttributeMaxDynamicSharedMemorySize, DM_SMEM);
    cudaFuncSetAttribute(updates_mma, cudaFuncAttributeMaxDynamicSharedMemorySize, UM_SMEM);

    dim3 lnb(32, 8);

    convert_w4<<<dim3(256, 4), 256>>>(pos_w1, pW1h, pW1l, pos_w2, pW2h, pW2l,
                                      Wk, pWkh, pWkl, Wv, pWvh, pWvl);

    ln_bf16_kernel<<<ROWS_BIG / 8, lnb>>>(feat, pos_ln_g, pos_ln_b, pP0h, pP0l, ROWS_BIG);
    gemm_mma<<<dim3(1, 2048, 1), 256, TG_SMEM>>>(pP0h, pP0l, pW1h, pW1l, pos_b1,
                                                 nullptr, pP1h, pP1l, 1,
                                                 nullptr, nullptr, nullptr, nullptr);
    gemm_mma<<<dim3(1, 2048, 1), 256, TG_SMEM>>>(pP1h, pP1l, pW2h, pW2l, pos_b2,
                                                 pA, nullptr, nullptr, 0,
                                                 nullptr, nullptr, nullptr, nullptr);
    ln_bf16_kernel<<<ROWS_BIG / 8, lnb>>>(pA, in_ln_g, in_ln_b, pP0h, pP0l, ROWS_BIG);
    // K and V both emitted as split bf16 (dual launch)
    gemm_mma<<<dim3(1, 2048, 2), 256, TG_SMEM>>>(pP0h, pP0l, pWkh, pWkl, nullptr,
                                                 nullptr, pKh, pKl, 0,
                                                 pWvh, pWvl, pVh, pVl);

    copy_kernel<<<ROWS_SL, 256>>>(cond, pSlots, ROWS_SL * DD);

    for (int it = 0; it < 3; it++) {
        ln_kernel<<<ROWS_SL / 8, lnb>>>(pSlots, slot_ln_g, slot_ln_b, pSn, ROWS_SL);
        gemm256_m32<<<dim3(2, 24), 256, QG_SMEM>>>(pSn, Wq, pQh, pQl, 256);
        dots_mma<<<dim3(16, HH, BB), 256, DM_SMEM>>>(pQh, pQl, pKh, pKl, pAttn);
        softmax_kernel<<<(BB * NTOK) / 128, 128>>>(pAttn, pAh, pAl, out_attn,
                                                   (it == 2) ? 1 : 0);
        updates_mma<<<dim3(HH, BB, 4), 256, UM_SMEM>>>(pAh, pAl, pVh, pVl,
                                                       pUpdp, pRsump, pUpd, pCnt);
        gemm256<<<dim3(6, 12, 2), 256, GEMM_SMEM>>>(pUpd, gru_wi, gru_bi, pGi, 768, 0,
                                                    pSlots, gru_wh, gru_bh, pGh, 768);
        gru_kernel<<<ROWS_SL, 256>>>(pGi, pGh, pSlots);
    }

    copy_kernel<<<ROWS_SL, 256>>>(pSlots, out, ROWS_SL * DD);
}

// round 17
// speedup vs baseline: 1.0543x; 1.0173x over previous
#include <cuda_runtime.h>
#include <cuda_bf16.h>
#include <cstdint>

// ---------------- problem constants ----------------
#define BB   32
#define NTOK 4096
#define SS   24
#define DD   256
#define HH   4
#define DHH  64
#define SH   96              // SS*HH
#define ROWS_BIG (BB*NTOK)   // 131072
#define ROWS_SL  (BB*SS)     // 768
#define EPS   1e-8f
#define LN_EPS 1e-5f
#define SCALE 0.125f         // 64^-0.5

// ---------------- device scratch ----------------
__device__ __nv_bfloat16 g_Kh[ROWS_BIG * DD];
__device__ __nv_bfloat16 g_Kl[ROWS_BIG * DD];
__device__ __nv_bfloat16 g_Vh[ROWS_BIG * DD];
__device__ __nv_bfloat16 g_Vl[ROWS_BIG * DD];
__device__ __nv_bfloat16 g_P0h[ROWS_BIG * DD];
__device__ __nv_bfloat16 g_P0l[ROWS_BIG * DD];
__device__ __nv_bfloat16 g_P1h[ROWS_BIG * DD];
__device__ __nv_bfloat16 g_P1l[ROWS_BIG * DD];
__device__ __nv_bfloat16 g_W1h[DD * DD], g_W1l[DD * DD];
__device__ __nv_bfloat16 g_W2h[DD * DD], g_W2l[DD * DD];
__device__ __nv_bfloat16 g_Wkh[DD * DD], g_Wkl[DD * DD];
__device__ __nv_bfloat16 g_Wvh[DD * DD], g_Wvl[DD * DD];
__device__ float g_slots[ROWS_SL * DD];
__device__ float g_sn[ROWS_SL * DD];
__device__ __nv_bfloat16 g_qh[ROWS_SL * DD];
__device__ __nv_bfloat16 g_ql[ROWS_SL * DD];
__device__ float g_attn[(size_t)BB * SH * NTOK];            // raw scores (pre-softmax)
__device__ __nv_bfloat16 g_ah[(size_t)BB * SH * NTOK];      // (attn+EPS) hi
__device__ __nv_bfloat16 g_al[(size_t)BB * SH * NTOK];      // (attn+EPS) lo
__device__ float g_updp[4 * ROWS_SL * DD];
__device__ float g_rsump[4 * BB * SH];
__device__ float g_upd[ROWS_SL * DD];
__device__ int   g_cnt[BB * HH];          // zero-init; self-resetting
__device__ float g_gi[ROWS_SL * 3 * DD];
__device__ float g_gh[ROWS_SL * 3 * DD];

// ---------------- helpers ----------------
__device__ __forceinline__ uint32_t smem_u32(const void* p) {
    uint32_t a;
    asm("{ .reg .u64 t; cvta.to.shared.u64 t, %1; cvt.u32.u64 %0, t; }" : "=r"(a) : "l"(p));
    return a;
}
__device__ __forceinline__ void cp16(uint32_t dst, const void* src) {
    asm volatile("cp.async.cg.shared.global [%0], [%1], 16;" :: "r"(dst), "l"(src));
}
#define CP_COMMIT() asm volatile("cp.async.commit_group;" ::: "memory")
#define CP_WAIT1()  asm volatile("cp.async.wait_group 1;" ::: "memory")
#define CP_WAIT0()  asm volatile("cp.async.wait_group 0;" ::: "memory")

#define LDSM_X4(R, ADDR) \
    asm volatile("ldmatrix.sync.aligned.m8n8.x4.shared.b16 {%0,%1,%2,%3}, [%4];" \
        : "=r"((R)[0]), "=r"((R)[1]), "=r"((R)[2]), "=r"((R)[3]) : "r"(ADDR))

#define LDSM_X4_T(R, ADDR) \
    asm volatile("ldmatrix.sync.aligned.m8n8.x4.trans.shared.b16 {%0,%1,%2,%3}, [%4];" \
        : "=r"((R)[0]), "=r"((R)[1]), "=r"((R)[2]), "=r"((R)[3]) : "r"(ADDR))

#define MMA16816(C, A, B0, B1) \
    asm volatile("mma.sync.aligned.m16n8k16.row.col.f32.bf16.bf16.f32 " \
        "{%0,%1,%2,%3}, {%4,%5,%6,%7}, {%8,%9}, {%0,%1,%2,%3};" \
        : "+f"((C)[0]), "+f"((C)[1]), "+f"((C)[2]), "+f"((C)[3]) \
        : "r"((A)[0]), "r"((A)[1]), "r"((A)[2]), "r"((A)[3]), "r"(B0), "r"(B1))

__device__ __forceinline__ uint32_t pack_bf2(float a, float b, float* ra, float* rb) {
    __nv_bfloat16 ha = __float2bfloat16(a), hb = __float2bfloat16(b);
    *ra = a - __bfloat162float(ha);
    *rb = b - __bfloat162float(hb);
    return (uint32_t)__bfloat16_as_ushort(ha) | ((uint32_t)__bfloat16_as_ushort(hb) << 16);
}
__device__ __forceinline__ uint32_t pack_bf2_lo(float a, float b) {
    __nv_bfloat16 ha = __float2bfloat16(a), hb = __float2bfloat16(b);
    return (uint32_t)__bfloat16_as_ushort(ha) | ((uint32_t)__bfloat16_as_ushort(hb) << 16);
}
__device__ __forceinline__ float sum_bf2(uint32_t p) {
    __nv_bfloat16 lo = __ushort_as_bfloat16((unsigned short)(p & 0xffff));
    __nv_bfloat16 hi = __ushort_as_bfloat16((unsigned short)(p >> 16));
    return __bfloat162float(lo) + __bfloat162float(hi);
}

// ---------------- mma.sync split-bf16 GEMM, cp.async 2-stage pipelined ----------
// Optional LIGHT fused LayerNorm epilogue (CTA owns full rows; stats via 8 KB
// partial-sum reduce, acc stays in registers -- no full-tile staging).
#define TG_STAGE 51200
#define TG_SMEM  (2 * TG_STAGE)
#define TG_AL    5120
#define TG_WH    10240
#define TG_WL    30720

__global__ __launch_bounds__(256, 2) void gemm_mma(
    const __nv_bfloat16* __restrict__ Ah, const __nv_bfloat16* __restrict__ Al,
    const __nv_bfloat16* Wh_, const __nv_bfloat16* Wl_,
    const float* __restrict__ bias, float* Cf,
    __nv_bfloat16* Chi, __nv_bfloat16* Clo, int relu,
    const float* __restrict__ ln_g, const float* __restrict__ ln_b,
    const __nv_bfloat16* Wh2, const __nv_bfloat16* Wl2,
    __nv_bfloat16* Chi2, __nv_bfloat16* Clo2)
{
    extern __shared__ char smem[];
    const __nv_bfloat16* Wh = Wh_;
    const __nv_bfloat16* Wl = Wl_;
    if (blockIdx.z == 1) { Wh = Wh2; Wl = Wl2; Cf = nullptr; Chi = Chi2; Clo = Clo2; }

    const int tid = threadIdx.x, lane = tid & 31, wid = tid >> 5;
    const int wm = wid >> 2, wn = wid & 3;
    const int bm = blockIdx.y * 64;
    const uint32_t sb = smem_u32(smem);

    const int r = tid >> 2, q = tid & 3;
    const uint32_t stA = (uint32_t)(r * 80 + q * 16);
    const size_t goA = (size_t)(bm + r) * 512 + q * 16;

    float acc[2][8][4];
#pragma unroll
    for (int i = 0; i < 2; i++)
#pragma unroll
        for (int j = 0; j < 8; j++)
#pragma unroll
            for (int e = 0; e < 4; e++) acc[i][j][e] = 0.f;

    {
        cp16(sb + stA,         (const char*)Ah + goA);
        cp16(sb + TG_AL + stA, (const char*)Al + goA);
#pragma unroll
        for (int u = 0; u < 4; u++) {
            uint32_t rw = (uint32_t)(r + 64 * u);
            uint32_t st = rw * 80 + q * 16;
            size_t go = (size_t)rw * 512 + q * 16;
            cp16(sb + TG_WH + st, (const char*)Wh + go);
            cp16(sb + TG_WL + st, (const char*)Wl + go);
        }
        CP_COMMIT();
    }

    for (int kc = 0; kc < 8; kc++) {
        if (kc < 7) {
            uint32_t d = sb + ((kc + 1) & 1) * TG_STAGE;
            size_t off = (size_t)(kc + 1) * 64;
            cp16(d + stA,         (const char*)Ah + goA + off);
            cp16(d + TG_AL + stA, (const char*)Al + goA + off);
#pragma unroll
            for (int u = 0; u < 4; u++) {
                uint32_t rw = (uint32_t)(r + 64 * u);
                uint32_t st = rw * 80 + q * 16;
                size_t go = (size_t)rw * 512 + q * 16 + off;
                cp16(d + TG_WH + st, (const char*)Wh + go);
                cp16(d + TG_WL + st, (const char*)Wl + go);
            }
            CP_COMMIT();
            CP_WAIT1();
        } else {
            CP_WAIT0();
        }
        __syncthreads();
        uint32_t stg = sb + (kc & 1) * TG_STAGE;
#pragma unroll
        for (int kk = 0; kk < 2; kk++) {
            uint32_t a_h[2][4], a_l[2][4], bfr[4][4];
            uint32_t acol  = kk * 32 + (lane >> 4) * 16;
            uint32_t arow0 = wm * 32 + (lane & 15);
            uint32_t bcol  = kk * 32 + ((lane >> 3) & 1) * 16;
            uint32_t nrowb = wn * 64 + ((lane >> 4) & 1) * 8 + (lane & 7);
            LDSM_X4(a_h[0], stg + arow0 * 80 + acol);
            LDSM_X4(a_h[1], stg + (arow0 + 16) * 80 + acol);
#pragma unroll
            for (int ng = 0; ng < 4; ng++)
                LDSM_X4(bfr[ng], stg + TG_WH + (nrowb + ng * 16) * 80 + bcol);
#pragma unroll
            for (int mt = 0; mt < 2; mt++)
#pragma unroll
                for (int nt = 0; nt < 8; nt++) {
                    int ng = nt >> 1, hb = (nt & 1) * 2;
                    MMA16816(acc[mt][nt], a_h[mt], bfr[ng][hb], bfr[ng][hb + 1]);
                }
            LDSM_X4(a_l[0], stg + TG_AL + arow0 * 80 + acol);
            LDSM_X4(a_l[1], stg + TG_AL + (arow0 + 16) * 80 + acol);
#pragma unroll
            for (int mt = 0; mt < 2; mt++)
#pragma unroll
                for (int nt = 0; nt < 8; nt++) {
                    int ng = nt >> 1, hb = (nt & 1) * 2;
                    MMA16816(acc[mt][nt], a_l[mt], bfr[ng][hb], bfr[ng][hb + 1]);
                }
#pragma unroll
            for (int ng = 0; ng < 4; ng++)
                LDSM_X4(bfr[ng], stg + TG_WL + (nrowb + ng * 16) * 80 + bcol);
#pragma unroll
            for (int mt = 0; mt < 2; mt++)
#pragma unroll
                for (int nt = 0; nt < 8; nt++) {
                    int ng = nt >> 1, hb = (nt & 1) * 2;
                    MMA16816(acc[mt][nt], a_h[mt], bfr[ng][hb], bfr[ng][hb + 1]);
                }
        }
        __syncthreads();
    }

    const int g = lane >> 2, tg = lane & 3;

    if (ln_g) {
        // ---- light fused LN: bias add, register-resident stats reduce ----
        float* ssum = (float*)smem;            // [64][16]
        float* ssq  = ssum + 64 * 16;          // [64][16]
        float* smean = ssq + 64 * 16;          // [64]
        float* sinv  = smean + 64;             // [64]
        // bias add into acc
#pragma unroll
        for (int mt = 0; mt < 2; mt++)
#pragma unroll
            for (int nt = 0; nt < 8; nt++) {
                int col = wn * 64 + nt * 8 + tg * 2;
                float b0 = bias[col], b1 = bias[col + 1];
#pragma unroll
                for (int half = 0; half < 2; half++) {
                    acc[mt][nt][half * 2 + 0] += b0;
                    acc[mt][nt][half * 2 + 1] += b1;
                }
            }
        // per-thread partial stats per owned row
        const int cid = wn * 4 + tg;   // 0..15 contributor per row
#pragma unroll
        for (int mt = 0; mt < 2; mt++)
#pragma unroll
            for (int half = 0; half < 2; half++) {
                float s = 0.f, qq2 = 0.f;
#pragma unroll
                for (int nt = 0; nt < 8; nt++) {
                    float v0 = acc[mt][nt][half * 2 + 0];
                    float v1 = acc[mt][nt][half * 2 + 1];
                    s += v0 + v1;
                    qq2 += v0 * v0 + v1 * v1;
                }
                int row = wm * 32 + mt * 16 + g + half * 8;
                ssum[row * 16 + cid] = s;
                ssq[row * 16 + cid] = qq2;
            }
        __syncthreads();
        if (tid < 64) {
            float s = 0.f, qq2 = 0.f;
#pragma unroll
            for (int c = 0; c < 16; c++) { s += ssum[tid * 16 + c]; qq2 += ssq[tid * 16 + c]; }
            float mean = s * (1.f / 256.f);
            float var  = qq2 * (1.f / 256.f) - mean * mean;
            smean[tid] = mean;
            sinv[tid] = rsqrtf(var + LN_EPS);
        }
        __syncthreads();
#pragma unroll
        for (int mt = 0; mt < 2; mt++)
#pragma unroll
            for (int half = 0; half < 2; half++) {
                int row = wm * 32 + mt * 16 + g + half * 8;
                float mean = smean[row], inv = sinv[row];
                size_t gbase = (size_t)(bm + row) * 256;
#pragma unroll
                for (int nt = 0; nt < 8; nt++) {
                    int col = wn * 64 + nt * 8 + tg * 2;
                    float v0 = (acc[mt][nt][half * 2 + 0] - mean) * inv * ln_g[col] + ln_b[col];
                    float v1 = (acc[mt][nt][half * 2 + 1] - mean) * inv * ln_g[col + 1] + ln_b[col + 1];
                    float r0, r1;
                    uint32_t hp = pack_bf2(v0, v1, &r0, &r1);
                    *(uint32_t*)(Chi + gbase + col) = hp;
                    *(uint32_t*)(Clo + gbase + col) = pack_bf2_lo(r0, r1);
                }
            }
        return;
    }

#pragma unroll
    for (int mt = 0; mt < 2; mt++)
#pragma unroll
        for (int nt = 0; nt < 8; nt++)
#pragma unroll
            for (int half = 0; half < 2; half++) {
                int row = bm + wm * 32 + mt * 16 + g + half * 8;
                int col = wn * 64 + nt * 8 + tg * 2;
                float v0 = acc[mt][nt][half * 2 + 0];
                float v1 = acc[mt][nt][half * 2 + 1];
                if (bias) { v0 += bias[col]; v1 += bias[col + 1]; }
                if (relu) { v0 = fmaxf(v0, 0.f); v1 = fmaxf(v1, 0.f); }
                size_t o = (size_t)row * 256 + col;
                if (Cf) *(float2*)(Cf + o) = make_float2(v0, v1);
                if (Chi) {
                    float r0, r1;
                    uint32_t hp = pack_bf2(v0, v1, &r0, &r1);
                    *(uint32_t*)(Chi + o) = hp;
                    *(uint32_t*)(Clo + o) = pack_bf2_lo(r0, r1);
                }
            }
}

// ---------------- dots via mma: attn[b,i*4+h,n] = SCALE * q.K^T (split bf16) -----
#define DM_QH 0
#define DM_QL 4608
#define DM_KH 9216
#define DM_KL 46080
#define DM_SMEM 82944

__global__ __launch_bounds__(256, 2) void dots_mma(
    const __nv_bfloat16* __restrict__ qh, const __nv_bfloat16* __restrict__ ql,
    const __nv_bfloat16* __restrict__ Kh, const __nv_bfloat16* __restrict__ Kl,
    float* __restrict__ attn)
{
    extern __shared__ char smem[];
    const int b = blockIdx.z, h = blockIdx.y, n0 = blockIdx.x * 256;
    const int tid = threadIdx.x, lane = tid & 31, wn = tid >> 5;
    const uint32_t sb = smem_u32(smem);

#pragma unroll
    for (int u = 0; u < 8; u++) {
        int idx = u * 256 + tid;
        int row = idx >> 3, qq = idx & 7;
        uint32_t st = (uint32_t)(row * 144 + qq * 16);
        size_t go = ((size_t)(b * NTOK + n0 + row) * 256 + h * DHH) * 2 + qq * 16;
        cp16(sb + DM_KH + st, (const char*)Kh + go);
        cp16(sb + DM_KL + st, (const char*)Kl + go);
    }
    CP_COMMIT();
    {
        int row = tid >> 3, qq = tid & 7;
        uint32_t st = (uint32_t)(row * 144 + qq * 16);
        if (row < SS) {
            size_t go = ((size_t)(b * SS + row) * 256 + h * DHH) * 2 + qq * 16;
            *(uint4*)(smem + DM_QH + st) = *(const uint4*)((const char*)qh + go);
            *(uint4*)(smem + DM_QL + st) = *(const uint4*)((const char*)ql + go);
        } else {
            uint4 z = make_uint4(0, 0, 0, 0);
            *(uint4*)(smem + DM_QH + st) = z;
            *(uint4*)(smem + DM_QL + st) = z;
        }
    }
    CP_WAIT0();
    __syncthreads();

    float acc[2][4][4];
#pragma unroll
    for (int i = 0; i < 2; i++)
#pragma unroll
        for (int j = 0; j < 4; j++)
#pragma unroll
            for (int e = 0; e < 4; e++) acc[i][j][e] = 0.f;

#pragma unroll
    for (int ks = 0; ks < 4; ks++) {
        uint32_t a_h[2][4], a_l[2][4], bfr[2][4];
        uint32_t acol = ks * 32 + (lane >> 4) * 16;
        uint32_t arow = (uint32_t)(lane & 15);
        uint32_t bcol = ks * 32 + ((lane >> 3) & 1) * 16;
        uint32_t nrow = (uint32_t)(wn * 32 + ((lane >> 4) & 1) * 8 + (lane & 7));
        LDSM_X4(a_h[0], sb + DM_QH + arow * 144 + acol);
        LDSM_X4(a_h[1], sb + DM_QH + (arow + 16) * 144 + acol);
        LDSM_X4(bfr[0], sb + DM_KH + nrow * 144 + bcol);
        LDSM_X4(bfr[1], sb + DM_KH + (nrow + 16) * 144 + bcol);
#pragma unroll
        for (int mt = 0; mt < 2; mt++)
#pragma unroll
            for (int nt = 0; nt < 4; nt++) {
                int ng = nt >> 1, hb = (nt & 1) * 2;
                MMA16816(acc[mt][nt], a_h[mt], bfr[ng][hb], bfr[ng][hb + 1]);
            }
        LDSM_X4(a_l[0], sb + DM_QL + arow * 144 + acol);
        LDSM_X4(a_l[1], sb + DM_QL + (arow + 16) * 144 + acol);
#pragma unroll
        for (int mt = 0; mt < 2; mt++)
#pragma unroll
            for (int nt = 0; nt < 4; nt++) {
                int ng = nt >> 1, hb = (nt & 1) * 2;
                MMA16816(acc[mt][nt], a_l[mt], bfr[ng][hb], bfr[ng][hb + 1]);
            }
        LDSM_X4(bfr[0], sb + DM_KL + nrow * 144 + bcol);
        LDSM_X4(bfr[1], sb + DM_KL + (nrow + 16) * 144 + bcol);
#pragma unroll
        for (int mt = 0; mt < 2; mt++)
#pragma unroll
            for (int nt = 0; nt < 4; nt++) {
                int ng = nt >> 1, hb = (nt & 1) * 2;
                MMA16816(acc[mt][nt], a_h[mt], bfr[ng][hb], bfr[ng][hb + 1]);
            }
    }

    const int g = lane >> 2, tg = lane & 3;
#pragma unroll
    for (int mt = 0; mt < 2; mt++)
#pragma unroll
        for (int nt = 0; nt < 4; nt++)
#pragma unroll
            for (int half = 0; half < 2; half++) {
                if (mt == 1 && half == 1) continue;
                int row = mt * 16 + g + half * 8;
                int col = n0 + wn * 32 + nt * 8 + tg * 2;
                float v0 = acc[mt][nt][half * 2 + 0] * SCALE;
                float v1 = acc[mt][nt][half * 2 + 1] * SCALE;
                *(float2*)(attn + ((size_t)b * SH + row * HH + h) * NTOK + col)
                    = make_float2(v0, v1);
            }
}

// ---------------- updates via mma: updT[d, i] = V^T @ (attn+EPS)^T ----------------
#define UM_VH 0
#define UM_VL 36864
#define UM_AH 73728
#define UM_AL (UM_AH + 32 * 528)
#define UM_SMEM (UM_AL + 32 * 528)      // 107520 B

__global__ __launch_bounds__(256, 2) void updates_mma(
    const __nv_bfloat16* __restrict__ ah, const __nv_bfloat16* __restrict__ al,
    const __nv_bfloat16* __restrict__ Vh, const __nv_bfloat16* __restrict__ Vl,
    float* __restrict__ updp, float* __restrict__ rsump,
    float* __restrict__ upd, int* __restrict__ cnt)
{
    extern __shared__ char smem[];
    __shared__ int s_last;
    const int h = blockIdx.x, b = blockIdx.y, zc = blockIdx.z;
    const int tid = threadIdx.x, lane = tid & 31, wid = tid >> 5;
    const int wm = wid >> 1, wn2 = wid & 1;
    const uint32_t sb = smem_u32(smem);

    for (int idx = tid; idx < 8 * 33; idx += 256) {
        int row = 24 + (idx / 33), qq = idx % 33;
        uint4 z = make_uint4(0, 0, 0, 0);
        *(uint4*)(smem + UM_AH + row * 528 + qq * 16) = z;
        *(uint4*)(smem + UM_AL + row * 528 + qq * 16) = z;
    }

    float acc[2][4];
#pragma unroll
    for (int i = 0; i < 2; i++)
#pragma unroll
        for (int e = 0; e < 4; e++) acc[i][e] = 0.f;
    float rsum = 0.f;
    const int rrow = tid >> 3;
    const int rq0  = (tid & 7) * 4;

    for (int c = 0; c < 4; c++) {
        int j0 = zc * 1024 + c * 256;
        __syncthreads();
#pragma unroll
        for (int u = 0; u < 8; u++) {
            int idx = u * 256 + tid;
            int row = idx >> 3, qq = idx & 7;
            uint32_t st = (uint32_t)(row * 144 + qq * 16);
            size_t go = ((size_t)(b * NTOK + j0 + row) * 256 + h * DHH) * 2 + qq * 16;
            cp16(sb + UM_VH + st, (const char*)Vh + go);
            cp16(sb + UM_VL + st, (const char*)Vl + go);
        }
#pragma unroll
        for (int u = 0; u < 3; u++) {
            int idx = u * 256 + tid;
            int row = idx >> 5, qq = idx & 31;
            uint32_t st = (uint32_t)(row * 528 + qq * 16);
            size_t go = ((size_t)(b * SH + row * HH + h) * NTOK + j0) * 2 + qq * 16;
            cp16(sb + UM_AH + st, (const char*)ah + go);
            cp16(sb + UM_AL + st, (const char*)al + go);
        }
        CP_COMMIT();
        CP_WAIT0();
        __syncthreads();

        if (rrow < SS) {
#pragma unroll
            for (int u = 0; u < 4; u++) {
                uint4 hv = *(uint4*)(smem + UM_AH + rrow * 528 + (rq0 + u) * 16);
                uint4 lv = *(uint4*)(smem + UM_AL + rrow * 528 + (rq0 + u) * 16);
                rsum += sum_bf2(hv.x) + sum_bf2(hv.y) + sum_bf2(hv.z) + sum_bf2(hv.w);
                rsum += sum_bf2(lv.x) + sum_bf2(lv.y) + sum_bf2(lv.z) + sum_bf2(lv.w);
            }
        }

#pragma unroll 4
        for (int ks = 0; ks < 16; ks++) {
            uint32_t a_h[4], a_l[4], b_h[4], b_l[4];
            uint32_t krow = (uint32_t)(ks * 16 + (lane & 7) + ((lane >> 4) & 1) * 8);
            uint32_t acb  = (uint32_t)(wm * 32 + ((lane >> 3) & 1) * 16);
            uint32_t nrow = (uint32_t)(wn2 * 16 + ((lane >> 4) & 1) * 8 + (lane & 7));
            uint32_t bcb  = (uint32_t)(ks * 32 + ((lane >> 3) & 1) * 16);
            LDSM_X4_T(a_h, sb + UM_VH + krow * 144 + acb);
            LDSM_X4(b_h, sb + UM_AH + nrow * 528 + bcb);
#pragma unroll
            for (int nf = 0; nf < 2; nf++)
                MMA16816(acc[nf], a_h, b_h[nf * 2], b_h[nf * 2 + 1]);
            LDSM_X4_T(a_l, sb + UM_VL + krow * 144 + acb);
#pragma unroll
            for (int nf = 0; nf < 2; nf++)
                MMA16816(acc[nf], a_l, b_h[nf * 2], b_h[nf * 2 + 1]);
            LDSM_X4(b_l, sb + UM_AL + nrow * 528 + bcb);
#pragma unroll
            for (int nf = 0; nf < 2; nf++)
                MMA16816(acc[nf], a_h, b_l[nf * 2], b_l[nf * 2 + 1]);
        }
    }

#pragma unroll
    for (int o = 4; o > 0; o >>= 1)
        rsum += __shfl_down_sync(0xffffffffu, rsum, o, 8);
    if ((tid & 7) == 0 && rrow < SS)
        rsump[zc * (BB * SH) + b * SH + rrow * HH + h] = rsum;

    const int g = lane >> 2, tg = lane & 3;
#pragma unroll
    for (int nf = 0; nf < 2; nf++)
#pragma unroll
        for (int hf = 0; hf < 2; hf++) {
            int d = wm * 16 + g + hf * 8;
            int i0 = wn2 * 16 + nf * 8 + tg * 2;
            if (i0 < SS) {
                float v0 = acc[nf][hf * 2 + 0];
                float v1 = acc[nf][hf * 2 + 1];
                updp[((size_t)zc * ROWS_SL + b * SS + i0) * DD + h * DHH + d] = v0;
                updp[((size_t)zc * ROWS_SL + b * SS + i0 + 1) * DD + h * DHH + d] = v1;
            }
        }

    __threadfence();
    if (tid == 0) {
        int old = atomicAdd(&cnt[b * HH + h], 1);
        s_last = (old == 3);
        if (s_last) cnt[b * HH + h] = 0;
    }
    __syncthreads();
    if (s_last) {
        for (int t = tid; t < SS * 64; t += 256) {
            int i = t >> 6, d = t & 63;
            size_t o = ((size_t)b * SS + i) * DD + h * DHH + d;
            float s = updp[o] + updp[(size_t)ROWS_SL * DD + o]
                    + updp[2 * (size_t)ROWS_SL * DD + o] + updp[3 * (size_t)ROWS_SL * DD + o];
            int ri = b * SH + i * HH + h;
            float r = rsump[ri] + rsump[BB * SH + ri] + rsump[2 * BB * SH + ri]
                    + rsump[3 * BB * SH + ri];
            upd[o] = s / r;
        }
    }
}

// ---------------- W transpose + bf16 split (4 weights, one launch) ----------------
__global__ void convert_w4(
    const float* __restrict__ W0, __nv_bfloat16* __restrict__ H0, __nv_bfloat16* __restrict__ L0,
    const float* __restrict__ W1, __nv_bfloat16* __restrict__ H1, __nv_bfloat16* __restrict__ L1,
    const float* __restrict__ W2, __nv_bfloat16* __restrict__ H2, __nv_bfloat16* __restrict__ L2,
    const float* __restrict__ W3, __nv_bfloat16* __restrict__ H3, __nv_bfloat16* __restrict__ L3)
{
    const float* W; __nv_bfloat16 *Hh, *Hl;
    switch (blockIdx.y) {
        case 0: W = W0; Hh = H0; Hl = L0; break;
        case 1: W = W1; Hh = H1; Hl = L1; break;
        case 2: W = W2; Hh = H2; Hl = L2; break;
        default: W = W3; Hh = H3; Hl = L3; break;
    }
    int k = blockIdx.x;
    int n = threadIdx.x;
    float v = W[k * DD + n];
    __nv_bfloat16 h = __float2bfloat16(v);
    Hh[n * DD + k] = h;
    Hl[n * DD + k] = __float2bfloat16(v - __bfloat162float(h));
}

// ---------------- LayerNorm (fp32 out, slots path) ----------------
__global__ void ln_kernel(const float* __restrict__ x, const float* __restrict__ g,
                          const float* __restrict__ b, float* __restrict__ y, int rows)
{
    int row = blockIdx.x * 8 + threadIdx.y;
    if (row >= rows) return;
    int lane = threadIdx.x;
    const float4* xr = (const float4*)(x + (size_t)row * DD);
    float4 v0 = xr[lane];
    float4 v1 = xr[lane + 32];
    float s  = v0.x + v0.y + v0.z + v0.w + v1.x + v1.y + v1.z + v1.w;
    float sq = v0.x*v0.x + v0.y*v0.y + v0.z*v0.z + v0.w*v0.w
             + v1.x*v1.x + v1.y*v1.y + v1.z*v1.z + v1.w*v1.w;
#pragma unroll
    for (int o = 16; o > 0; o >>= 1) {
        s  += __shfl_xor_sync(0xffffffffu, s,  o);
        sq += __shfl_xor_sync(0xffffffffu, sq, o);
    }
    float mean = s * (1.f / 256.f);
    float var  = sq * (1.f / 256.f) - mean * mean;
    float inv  = rsqrtf(var + LN_EPS);
    const float4* g4 = (const float4*)g;
    const float4* b4 = (const float4*)b;
    float4* yr = (float4*)(y + (size_t)row * DD);
    float4 gg = g4[lane], bb = b4[lane], o0;
    o0.x = (v0.x - mean) * inv * gg.x + bb.x;
    o0.y = (v0.y - mean) * inv * gg.y + bb.y;
    o0.z = (v0.z - mean) * inv * gg.z + bb.z;
    o0.w = (v0.w - mean) * inv * gg.w + bb.w;
    yr[lane] = o0;
    gg = g4[lane + 32]; bb = b4[lane + 32];
    float4 o1;
    o1.x = (v1.x - mean) * inv * gg.x + bb.x;
    o1.y = (v1.y - mean) * inv * gg.y + bb.y;
    o1.z = (v1.z - mean) * inv * gg.z + bb.z;
    o1.w = (v1.w - mean) * inv * gg.w + bb.w;
    yr[lane + 32] = o1;
}

// ---------------- LayerNorm emitting bf16 hi/lo split (input feats) ---------------
__global__ void ln_bf16_kernel(const float* __restrict__ x, const float* __restrict__ g,
                               const float* __restrict__ b,
                               __nv_bfloat16* __restrict__ yh, __nv_bfloat16* __restrict__ yl,
                               int rows)
{
    int row = blockIdx.x * 8 + threadIdx.y;
    if (row >= rows) return;
    int lane = threadIdx.x;
    const float4* xr = (const float4*)(x + (size_t)row * DD);
    float4 v0 = xr[lane];
    float4 v1 = xr[lane + 32];
    float s  = v0.x + v0.y + v0.z + v0.w + v1.x + v1.y + v1.z + v1.w;
    float sq = v0.x*v0.x + v0.y*v0.y + v0.z*v0.z + v0.w*v0.w
             + v1.x*v1.x + v1.y*v1.y + v1.z*v1.z + v1.w*v1.w;
#pragma unroll
    for (int o = 16; o > 0; o >>= 1) {
        s  += __shfl_xor_sync(0xffffffffu, s,  o);
        sq += __shfl_xor_sync(0xffffffffu, sq, o);
    }
    float mean = s * (1.f / 256.f);
    float var  = sq * (1.f / 256.f) - mean * mean;
    float inv  = rsqrtf(var + LN_EPS);
    const float4* g4 = (const float4*)g;
    const float4* b4 = (const float4*)b;
    size_t base = (size_t)row * DD;
#pragma unroll
    for (int half = 0; half < 2; half++) {
        float4 v = half ? v1 : v0;
        float4 gg = g4[lane + half * 32], bb = b4[lane + half * 32];
        float4 o;
        o.x = (v.x - mean) * inv * gg.x + bb.x;
        o.y = (v.y - mean) * inv * gg.y + bb.y;
        o.z = (v.z - mean) * inv * gg.z + bb.z;
        o.w = (v.w - mean) * inv * gg.w + bb.w;
        float r0, r1, r2, r3;
        uint2 hp, lp;
        hp.x = pack_bf2(o.x, o.y, &r0, &r1);
        hp.y = pack_bf2(o.z, o.w, &r2, &r3);
        lp.x = pack_bf2_lo(r0, r1);
        lp.y = pack_bf2_lo(r2, r3);
        size_t off = base + half * 128 + lane * 4;
        *(uint2*)(yh + off) = hp;
        *(uint2*)(yl + off) = lp;
    }
}

// ---------------- SIMT GEMM, 64x128 tile (dual via blockIdx.z), fp32 out -------
#define GEMM_AS_PAD 68
#define GEMM_SMEM_FLOATS (64 * GEMM_AS_PAD + 64 * 128)

__global__ __launch_bounds__(256) void gemm256(
    const float* A, const float* W, const float* bias, float* C, int N, int relu,
    const float* A1, const float* W1, const float* bias1, float* C1, int N1)
{
    if (blockIdx.z == 1) { A = A1; W = W1; bias = bias1; C = C1; N = N1; }
    extern __shared__ float sm[];
    float* As = sm;
    float* Bs = sm + 64 * GEMM_AS_PAD;
    const int bn = blockIdx.x * 128;
    const int bm = blockIdx.y * 64;
    const int tid = threadIdx.x;
    const int tx = tid & 15;
    const int ty = tid >> 4;
    float acc[4][8];
#pragma unroll
    for (int i = 0; i < 4; i++)
#pragma unroll
        for (int j = 0; j < 8; j++) acc[i][j] = 0.f;

    for (int k0 = 0; k0 < 256; k0 += 64) {
#pragma unroll
        for (int u = 0; u < 4; u++) {
            int f4 = tid + 256 * u;
            int r = f4 >> 4, c4 = f4 & 15;
            float4 v = *(const float4*)(A + (size_t)(bm + r) * DD + (k0 + c4 * 4));
            As[(c4 * 4 + 0) * GEMM_AS_PAD + r] = v.x;
            As[(c4 * 4 + 1) * GEMM_AS_PAD + r] = v.y;
            As[(c4 * 4 + 2) * GEMM_AS_PAD + r] = v.z;
            As[(c4 * 4 + 3) * GEMM_AS_PAD + r] = v.w;
        }
#pragma unroll
        for (int u = 0; u < 8; u++) {
            int f4 = tid + 256 * u;
            int r = f4 >> 5, c4 = f4 & 31;
            *(float4*)(&Bs[r * 128 + c4 * 4]) =
                *(const float4*)(W + (size_t)(k0 + r) * N + (bn + c4 * 4));
        }
        __syncthreads();
#pragma unroll 8
        for (int k = 0; k < 64; k++) {
            float a[4], bfr[8];
            *(float4*)(a) = *(const float4*)(&As[k * GEMM_AS_PAD + ty * 4]);
            *(float4*)(bfr)     = *(const float4*)(&Bs[k * 128 + tx * 8]);
            *(float4*)(bfr + 4) = *(const float4*)(&Bs[k * 128 + tx * 8 + 4]);
#pragma unroll
            for (int i = 0; i < 4; i++)
#pragma unroll
                for (int j = 0; j < 8; j++)
                    acc[i][j] = fmaf(a[i], bfr[j], acc[i][j]);
        }
        __syncthreads();
    }
    float bv[8];
#pragma unroll
    for (int j = 0; j < 8; j++) bv[j] = bias ? bias[bn + tx * 8 + j] : 0.f;
#pragma unroll
    for (int i = 0; i < 4; i++) {
        float* crow = C + (size_t)(bm + ty * 4 + i) * N + bn + tx * 8;
#pragma unroll
        for (int j = 0; j < 8; j += 4) {
            float4 o;
            o.x = acc[i][j + 0] + bv[j + 0];
            o.y = acc[i][j + 1] + bv[j + 1];
            o.z = acc[i][j + 2] + bv[j + 2];
            o.w = acc[i][j + 3] + bv[j + 3];
            if (relu) {
                o.x = fmaxf(o.x, 0.f); o.y = fmaxf(o.y, 0.f);
                o.z = fmaxf(o.z, 0.f); o.w = fmaxf(o.w, 0.f);
            }
            *(float4*)(crow + j) = o;
        }
    }
}

// ---------------- SIMT GEMM, 32x128 tile, split-bf16 out (q projection) --------
#define QG_AS_PAD 36
#define QG_SMEM_FLOATS (64 * QG_AS_PAD + 64 * 128)

__global__ __launch_bounds__(256) void gemm256_m32(
    const float* __restrict__ A, const float* __restrict__ W,
    __nv_bfloat16* __restrict__ Ch, __nv_bfloat16* __restrict__ Cl, int N)
{
    extern __shared__ float sm[];
    float* As = sm;
    float* Bs = sm + 64 * QG_AS_PAD;
    const int bn = blockIdx.x * 128;
    const int bm = blockIdx.y * 32;
    const int tid = threadIdx.x;
    const int tx = tid & 15;
    const int ty = tid >> 4;
    float acc[2][8];
#pragma unroll
    for (int i = 0; i < 2; i++)
#pragma unroll
        for (int j = 0; j < 8; j++) acc[i][j] = 0.f;

    for (int k0 = 0; k0 < 256; k0 += 64) {
#pragma unroll
        for (int u = 0; u < 2; u++) {
            int f4 = tid + 256 * u;
            int r = f4 >> 4, c4 = f4 & 15;
            float4 v = *(const float4*)(A + (size_t)(bm + r) * DD + (k0 + c4 * 4));
            As[(c4 * 4 + 0) * QG_AS_PAD + r] = v.x;
            As[(c4 * 4 + 1) * QG_AS_PAD + r] = v.y;
            As[(c4 * 4 + 2) * QG_AS_PAD + r] = v.z;
            As[(c4 * 4 + 3) * QG_AS_PAD + r] = v.w;
        }
#pragma unroll
        for (int u = 0; u < 8; u++) {
            int f4 = tid + 256 * u;
            int r = f4 >> 5, c4 = f4 & 31;
            *(float4*)(&Bs[r * 128 + c4 * 4]) =
                *(const float4*)(W + (size_t)(k0 + r) * N + (bn + c4 * 4));
        }
        __syncthreads();
#pragma unroll 8
        for (int k = 0; k < 64; k++) {
            float a0 = As[k * QG_AS_PAD + ty * 2];
            float a1 = As[k * QG_AS_PAD + ty * 2 + 1];
            float bfr[8];
            *(float4*)(bfr)     = *(const float4*)(&Bs[k * 128 + tx * 8]);
            *(float4*)(bfr + 4) = *(const float4*)(&Bs[k * 128 + tx * 8 + 4]);
#pragma unroll
            for (int j = 0; j < 8; j++) {
                acc[0][j] = fmaf(a0, bfr[j], acc[0][j]);
                acc[1][j] = fmaf(a1, bfr[j], acc[1][j]);
            }
        }
        __syncthreads();
    }
#pragma unroll
    for (int i = 0; i < 2; i++) {
        size_t rowo = (size_t)(bm + ty * 2 + i) * N + bn + tx * 8;
#pragma unroll
        for (int j = 0; j < 8; j += 4) {
            float r0, r1, r2, r3;
            uint2 hp, lp;
            hp.x = pack_bf2(acc[i][j + 0], acc[i][j + 1], &r0, &r1);
            hp.y = pack_bf2(acc[i][j + 2], acc[i][j + 3], &r2, &r3);
            lp.x = pack_bf2_lo(r0, r1);
            lp.y = pack_bf2_lo(r2, r3);
            *(uint2*)(Ch + rowo + j) = hp;
            *(uint2*)(Cl + rowo + j) = lp;
        }
    }
}

// ---------------- softmax: fp32 scores -> (attn+EPS) bf16 hi/lo + optional mean ----
__global__ __launch_bounds__(128) void softmax_kernel(const float* __restrict__ attn,
    __nv_bfloat16* __restrict__ oh, __nv_bfloat16* __restrict__ ol,
    float* __restrict__ out_attn, int write_mean)
{
    int idx = blockIdx.x * 128 + threadIdx.x;
    int b = idx >> 12, n = idx & 4095;
    const float* base = attn + (size_t)b * SH * NTOK + n;
    float vals[SH];
    float mx = -1e30f;
#pragma unroll
    for (int r = 0; r < SH; r++) {
        vals[r] = base[(size_t)r * NTOK];
        mx = fmaxf(mx, vals[r]);
    }
    float s = 0.f;
#pragma unroll
    for (int r = 0; r < SH; r++) { vals[r] = __expf(vals[r] - mx); s += vals[r]; }
    float inv = 1.f / s;
    size_t obase = (size_t)b * SH * NTOK + n;
#pragma unroll
    for (int r = 0; r < SH; r++) {
        vals[r] *= inv;
        float t = vals[r] + EPS;
        __nv_bfloat16 hi = __float2bfloat16(t);
        __nv_bfloat16 lo = __float2bfloat16(t - __bfloat162float(hi));
        oh[obase + (size_t)r * NTOK] = hi;
        ol[obase + (size_t)r * NTOK] = lo;
    }
    if (write_mean) {
#pragma unroll
        for (int i = 0; i < SS; i++) {
            float m = (vals[4*i] + vals[4*i+1] + vals[4*i+2] + vals[4*i+3]) * 0.25f;
            out_attn[((size_t)b * SS + i) * NTOK + n] = m;
        }
    }
}

// ---------------- GRU combine ----------------
__global__ void gru_kernel(const float* __restrict__ gi, const float* __restrict__ gh,
                           float* __restrict__ slots)
{
    int row = blockIdx.x;
    int col = threadIdx.x;
    size_t o = (size_t)row * 768;
    float ir = gi[o + col],       iz = gi[o + 256 + col], in_ = gi[o + 512 + col];
    float hr = gh[o + col],       hz = gh[o + 256 + col], hn  = gh[o + 512 + col];
    float hv = slots[(size_t)row * DD + col];
    float r  = 1.f / (1.f + __expf(-(ir + hr)));
    float zz = 1.f / (1.f + __expf(-(iz + hz)));
    float nn = tanhf(in_ + r * hn);
    slots[(size_t)row * DD + col] = (1.f - zz) * nn + zz * hv;
}

__global__ void copy_kernel(const float* __restrict__ src, float* __restrict__ dst, int n)
{
    int i = blockIdx.x * 256 + threadIdx.x;
    if (i < n) dst[i] = src[i];
}

// ---------------- host launch -----------------------------------------------------
extern "C" void kernel_launch(void* const* d_in, const int* in_sizes, int n_in,
                              void* d_out, int out_size)
{
    const float* feat      = (const float*)d_in[0];
    const float* cond      = (const float*)d_in[1];
    const float* pos_ln_g  = (const float*)d_in[2];
    const float* pos_ln_b  = (const float*)d_in[3];
    const float* pos_w1    = (const float*)d_in[4];
    const float* pos_b1    = (const float*)d_in[5];
    const float* pos_w2    = (const float*)d_in[6];
    const float* pos_b2    = (const float*)d_in[7];
    const float* in_ln_g   = (const float*)d_in[8];
    const float* in_ln_b   = (const float*)d_in[9];
    const float* slot_ln_g = (const float*)d_in[10];
    const float* slot_ln_b = (const float*)d_in[11];
    const float* Wq        = (const float*)d_in[12];
    const float* Wk        = (const float*)d_in[13];
    const float* Wv        = (const float*)d_in[14];
    const float* gru_wi    = (const float*)d_in[15];
    const float* gru_wh    = (const float*)d_in[16];
    const float* gru_bi    = (const float*)d_in[17];
    const float* gru_bh    = (const float*)d_in[18];
    float* out = (float*)d_out;
    float* out_attn = out + ROWS_SL * DD;

    float *pSlots, *pSn, *pAttn, *pUpdp, *pRsump, *pUpd, *pGi, *pGh;
    int* pCnt;
    __nv_bfloat16 *pKh, *pKl, *pVh, *pVl, *pQh, *pQl, *pAh, *pAl;
    __nv_bfloat16 *pP0h, *pP0l, *pP1h, *pP1l;
    __nv_bfloat16 *pW1h, *pW1l, *pW2h, *pW2l, *pWkh, *pWkl, *pWvh, *pWvl;
    cudaGetSymbolAddress((void**)&pKh, g_Kh);
    cudaGetSymbolAddress((void**)&pKl, g_Kl);
    cudaGetSymbolAddress((void**)&pVh, g_Vh);
    cudaGetSymbolAddress((void**)&pVl, g_Vl);
    cudaGetSymbolAddress((void**)&pP0h, g_P0h);
    cudaGetSymbolAddress((void**)&pP0l, g_P0l);
    cudaGetSymbolAddress((void**)&pP1h, g_P1h);
    cudaGetSymbolAddress((void**)&pP1l, g_P1l);
    cudaGetSymbolAddress((void**)&pW1h, g_W1h);
    cudaGetSymbolAddress((void**)&pW1l, g_W1l);
    cudaGetSymbolAddress((void**)&pW2h, g_W2h);
    cudaGetSymbolAddress((void**)&pW2l, g_W2l);
    cudaGetSymbolAddress((void**)&pWkh, g_Wkh);
    cudaGetSymbolAddress((void**)&pWkl, g_Wkl);
    cudaGetSymbolAddress((void**)&pWvh, g_Wvh);
    cudaGetSymbolAddress((void**)&pWvl, g_Wvl);
    cudaGetSymbolAddress((void**)&pSlots, g_slots);
    cudaGetSymbolAddress((void**)&pSn, g_sn);
    cudaGetSymbolAddress((void**)&pQh, g_qh);
    cudaGetSymbolAddress((void**)&pQl, g_ql);
    cudaGetSymbolAddress((void**)&pAttn, g_attn);
    cudaGetSymbolAddress((void**)&pAh, g_ah);
    cudaGetSymbolAddress((void**)&pAl, g_al);
    cudaGetSymbolAddress((void**)&pUpdp, g_updp);
    cudaGetSymbolAddress((void**)&pRsump, g_rsump);
    cudaGetSymbolAddress((void**)&pUpd, g_upd);
    cudaGetSymbolAddress((void**)&pCnt, g_cnt);
    cudaGetSymbolAddress((void**)&pGi, g_gi);
    cudaGetSymbolAddress((void**)&pGh, g_gh);

    const int GEMM_SMEM = GEMM_SMEM_FLOATS * 4;
    const int QG_SMEM   = QG_SMEM_FLOATS * 4;
    cudaFuncSetAttribute(gemm256, cudaFuncAttributeMaxDynamicSharedMemorySize, GEMM_SMEM);
    cudaFuncSetAttribute(gemm256_m32, cudaFuncAttributeMaxDynamicSharedMemorySize, QG_SMEM);
    cudaFuncSetAttribute(gemm_mma, cudaFuncAttributeMaxDynamicSharedMemorySize, TG_SMEM);
    cudaFuncSetAttribute(dots_mma, cudaFuncAttributeMaxDynamicSharedMemorySize, DM_SMEM);
    cudaFuncSetAttribute(updates_mma, cudaFuncAttributeMaxDynamicSharedMemorySize, UM_SMEM);

    dim3 lnb(32, 8);

    convert_w4<<<dim3(256, 4), 256>>>(pos_w1, pW1h, pW1l, pos_w2, pW2h, pW2l,
                                      Wk, pWkh, pWkl, Wv, pWvh, pWvl);

    ln_bf16_kernel<<<ROWS_BIG / 8, lnb>>>(feat, pos_ln_g, pos_ln_b, pP0h, pP0l, ROWS_BIG);
    // gemm1: relu + split -> P1
    gemm_mma<<<dim3(1, 2048, 1), 256, TG_SMEM>>>(pP0h, pP0l, pW1h, pW1l, pos_b1,
                                                 nullptr, pP1h, pP1l, 1,
                                                 nullptr, nullptr,
                                                 nullptr, nullptr, nullptr, nullptr);
    // gemm2 with LIGHT fused input-LN -> P0 split (no fp32 intermediate)
    gemm_mma<<<dim3(1, 2048, 1), 256, TG_SMEM>>>(pP1h, pP1l, pW2h, pW2l, pos_b2,
                                                 nullptr, pP0h, pP0l, 0,
                                                 in_ln_g, in_ln_b,
                                                 nullptr, nullptr, nullptr, nullptr);
    // K and V both emitted as split bf16 (dual launch)
    gemm_mma<<<dim3(1, 2048, 2), 256, TG_SMEM>>>(pP0h, pP0l, pWkh, pWkl, nullptr,
                                                 nullptr, pKh, pKl, 0,
                                                 nullptr, nullptr,
                                                 pWvh, pWvl, pVh, pVl);

    copy_kernel<<<ROWS_SL, 256>>>(cond, pSlots, ROWS_SL * DD);

    for (int it = 0; it < 3; it++) {
        ln_kernel<<<ROWS_SL / 8, lnb>>>(pSlots, slot_ln_g, slot_ln_b, pSn, ROWS_SL);
        gemm256_m32<<<dim3(2, 24), 256, QG_SMEM>>>(pSn, Wq, pQh, pQl, 256);
        dots_mma<<<dim3(16, HH, BB), 256, DM_SMEM>>>(pQh, pQl, pKh, pKl, pAttn);
        softmax_kernel<<<(BB * NTOK) / 128, 128>>>(pAttn, pAh, pAl, out_attn,
                                                   (it == 2) ? 1 : 0);
        updates_mma<<<dim3(HH, BB, 4), 256, UM_SMEM>>>(pAh, pAl, pVh, pVl,
                                                       pUpdp, pRsump, pUpd, pCnt);
        gemm256<<<dim3(6, 12, 2), 256, GEMM_SMEM>>>(pUpd, gru_wi, gru_bi, pGi, 768, 0,
                                                    pSlots, gru_wh, gru_bh, pGh, 768);
        gru_kernel<<<ROWS_SL, 256>>>(pGi, pGh, pSlots);
    }

    copy_kernel<<<ROWS_SL, 256>>>(pSlots, out, ROWS_SL * DD);
}